// round 4
// baseline (speedup 1.0000x reference)
#include <cuda_runtime.h>
#include <math.h>
#include <stdint.h>

#define NN 50000
#define EE 800000
#define EPSW 1e-5f

__device__ __forceinline__ float to_tf32(float x) {
    float y; asm("cvt.rna.tf32.f32 %0, %1;" : "=f"(y) : "f"(x)); return y;
}
__device__ __forceinline__ void mma8(float c[4], const uint32_t a[4], const uint32_t b[2]) {
    asm volatile("mma.sync.aligned.m16n8k8.row.col.f32.tf32.tf32.f32 "
                 "{%0,%1,%2,%3}, {%4,%5,%6,%7}, {%8,%9}, {%0,%1,%2,%3};"
                 : "+f"(c[0]), "+f"(c[1]), "+f"(c[2]), "+f"(c[3])
                 : "r"(a[0]), "r"(a[1]), "r"(a[2]), "r"(a[3]), "r"(b[0]), "r"(b[1]));
}

// ==================== scratch ====================
__device__ float g_deg[NN];
__device__ float g_logdeg[NN];
__device__ float g_amp[NN];
__device__ float g_att[NN];
__device__ float g_logsum;
__device__ int   g_rowptr[NN + 1];
__device__ int   g_cursor[NN];
__device__ int   g_col[EE];
__device__ float g_h0[(size_t)NN * 256];
__device__ float g_h1[(size_t)NN * 256];
__device__ float g_aggs[(size_t)NN * 1024];
__device__ float g_colsum[256];
__device__ float g_colsumsq[256];
__device__ float g_s[256];
__device__ float g_t[256];
__device__ float g_wc2[64 * 10];
__device__ float g_bc2[10];
// hi/lo interleaved: [n][k] -> (hi, lo) pair
__device__ float g_wt1[128 * 832 * 2];
__device__ float g_wt2[256 * 1664 * 2];
__device__ float g_wt3[128 * 3328 * 2];
__device__ float g_wt4[64 * 1664 * 2];

// ==================== preprocessing ====================
__global__ void k_init() {
    int i = blockIdx.x * blockDim.x + threadIdx.x;
    if (i < NN) g_deg[i] = 0.f;
    if (i < 256) { g_s[i] = 1.f; g_t[i] = 0.f; }
    if (i == 0) g_logsum = 0.f;
}
__global__ void k_degcnt(const int* __restrict__ ei) {
    int e = blockIdx.x * blockDim.x + threadIdx.x;
    if (e < EE) atomicAdd(&g_deg[ei[EE + e]], 1.f);
}
__global__ void k_logdeg() {
    int n = blockIdx.x * blockDim.x + threadIdx.x;
    float ld = 0.f;
    if (n < NN) { ld = log1pf(g_deg[n]); g_logdeg[n] = ld; }
    __shared__ float sh[256];
    sh[threadIdx.x] = ld;
    __syncthreads();
    for (int off = 128; off; off >>= 1) {
        if (threadIdx.x < off) sh[threadIdx.x] += sh[threadIdx.x + off];
        __syncthreads();
    }
    if (threadIdx.x == 0) atomicAdd(&g_logsum, sh[0]);
}
__global__ void k_scalers() {
    int n = blockIdx.x * blockDim.x + threadIdx.x;
    if (n >= NN) return;
    float delta = g_logsum / (float)NN;
    float ld = g_logdeg[n];
    g_amp[n] = ld / delta;
    g_att[n] = (ld > 0.f) ? delta / fmaxf(ld, 1e-6f) : 1.f;
}
__global__ void k_scan() {
    __shared__ int wsum[32];
    __shared__ int carry_s;
    int tid = threadIdx.x, lane = tid & 31, wid = tid >> 5;
    if (tid == 0) carry_s = 0;
    __syncthreads();
    for (int base = 0; base < NN; base += 1024) {
        int i = base + tid;
        int v = (i < NN) ? (int)g_deg[i] : 0;
        int x = v;
        #pragma unroll
        for (int off = 1; off < 32; off <<= 1) {
            int y = __shfl_up_sync(0xffffffffu, x, off);
            if (lane >= off) x += y;
        }
        if (lane == 31) wsum[wid] = x;
        __syncthreads();
        if (wid == 0) {
            int w = wsum[lane];
            #pragma unroll
            for (int off = 1; off < 32; off <<= 1) {
                int y = __shfl_up_sync(0xffffffffu, w, off);
                if (lane >= off) w += y;
            }
            wsum[lane] = w;
        }
        __syncthreads();
        int incl = x + (wid > 0 ? wsum[wid - 1] : 0);
        int carry = carry_s;
        if (i < NN) { g_rowptr[i] = carry + incl - v; g_cursor[i] = carry + incl - v; }
        __syncthreads();
        if (tid == 1023) carry_s = carry + incl;
        __syncthreads();
    }
    if (tid == 0) g_rowptr[NN] = carry_s;
}
__global__ void k_scatter(const int* __restrict__ ei) {
    int e = blockIdx.x * blockDim.x + threadIdx.x;
    if (e >= EE) return;
    int dst = ei[EE + e];
    int pos = atomicAdd(&g_cursor[dst], 1);
    g_col[pos] = ei[e];
}
// Wt[(n*K + k)*2 + {0,1}] = (tf32_hi, tf32_lo) of W[k][n]
__global__ void k_transpose(const float* __restrict__ W, float* __restrict__ Wt,
                            int K, int Nc) {
    int idx = blockIdx.x * blockDim.x + threadIdx.x;
    if (idx >= K * Nc) return;
    int n = idx / K, k = idx % K;
    float w = W[(size_t)k * Nc + n];
    float hi = to_tf32(w);
    float lo = to_tf32(w - hi);
    Wt[(size_t)idx * 2] = hi;
    Wt[(size_t)idx * 2 + 1] = lo;
}

// ==================== aggregation ====================
template <int DIN>
__global__ void k_agg(const float* __restrict__ in) {
    const int CH = DIN / 32;
    int warp = (blockIdx.x * blockDim.x + threadIdx.x) >> 5;
    int lane = threadIdx.x & 31;
    if (warp >= NN * CH) return;
    int n = warp / CH;
    int c = (warp % CH) * 32 + lane;
    float s = g_s[c], t = g_t[c];
    int beg = g_rowptr[n], end = g_rowptr[n + 1];
    float sum = 0.f, ss = 0.f, mn = INFINITY, mx = -INFINITY;
    for (int j = beg; j < end; j++) {
        int src = g_col[j];
        float v = in[(size_t)src * DIN + c];
        v = fmaf(s, v, t);
        sum += v; ss = fmaf(v, v, ss);
        mn = fminf(mn, v); mx = fmaxf(mx, v);
    }
    float deg = (float)(end - beg);
    float cnt = fmaxf(deg, 1.f);
    float mean = sum / cnt;
    float var = fmaxf(ss / cnt - mean * mean, 0.f);
    float sd = sqrtf(var + EPSW);
    bool has = end > beg;
    mn = has ? mn : 0.f;
    mx = has ? mx : 0.f;
    float* ag = g_aggs + (size_t)n * 4 * DIN;
    ag[c] = mean;
    ag[DIN + c] = mn;
    ag[2 * DIN + c] = mx;
    ag[3 * DIN + c] = sd;
}
__global__ void k_zerostats() {
    int c = threadIdx.x;
    if (c < 256) { g_colsum[c] = 0.f; g_colsumsq[c] = 0.f; }
}

// ==================== 3xTF32 mma.sync fused PNA GEMM ====================
// CTA 128(M) x 64(N), 4 warps (2M x 2N), warp tile 64x32 via m16n8k8.
// 3xTF32: acc += a_hi*b_hi + a_hi*b_lo + a_lo*b_hi  (fp32-grade precision).
// K runs over 13*DIN virtual rows:
//   [0,DIN):       A = BN-affine(in)     vs W rows [0,DIN)
//   [DIN,5DIN):    A = aggs              vs W rows [DIN,5DIN)
//   [5DIN,9DIN):   A = amp[row]*aggs     vs W rows [5DIN,9DIN)
//   [9DIN,13DIN):  A = att[row]*aggs     vs W rows [9DIN,13DIN)
// Epilogue: + bias, ReLU, store, column sum/sumsq for next BN.
template <int DIN, int DOUT>
__global__ void __launch_bounds__(128) k_gemm_mma(const float* __restrict__ in,
                                                  const float* __restrict__ Wt,
                                                  const float* __restrict__ bias,
                                                  float* __restrict__ out) {
    constexpr int K13 = 13 * DIN;
    __shared__ float scs[64], scss[64];
    const int tid = threadIdx.x, lane = tid & 31, wid = tid >> 5;
    const int warpM = wid & 1, warpN = wid >> 1;
    const int m0 = blockIdx.x * 128, n0 = blockIdx.y * 64;
    const int gr = lane >> 2, tig = lane & 3;

    if (tid < 64) { scs[tid] = 0.f; scss[tid] = 0.f; }

    float acc[4][4][4];
    #pragma unroll
    for (int i = 0; i < 4; i++)
        #pragma unroll
        for (int j = 0; j < 4; j++)
            #pragma unroll
            for (int q = 0; q < 4; q++) acc[i][j][q] = 0.f;

    int r0[4], r1[4], r0c[4], r1c[4];
    float amp0[4], amp1[4], att0[4], att1[4];
    #pragma unroll
    for (int i = 0; i < 4; i++) {
        r0[i] = m0 + warpM * 64 + i * 16 + gr;
        r1[i] = r0[i] + 8;
        r0c[i] = r0[i] < NN ? r0[i] : NN - 1;
        r1c[i] = r1[i] < NN ? r1[i] : NN - 1;
        amp0[i] = g_amp[r0c[i]]; amp1[i] = g_amp[r1c[i]];
        att0[i] = g_att[r0c[i]]; att1[i] = g_att[r1c[i]];
    }
    // B pointers: pair-per-element rows of Wt
    const float2* bp[4];
    #pragma unroll
    for (int j = 0; j < 4; j++)
        bp[j] = (const float2*)Wt + (size_t)(n0 + warpN * 32 + j * 8 + gr) * K13;

    // helper lambdas (forced inline by templates/unroll)
    #define SPLIT(x, hi, lo) do { float _h = to_tf32(x); hi = __float_as_uint(_h); \
                                  lo = __float_as_uint(to_tf32((x) - _h)); } while (0)

    // ---- region 0: BN-affine input vs W[0:DIN) ----
    #pragma unroll 1
    for (int k0 = 0; k0 < DIN; k0 += 8) {
        const int kc = k0 + tig;
        const float s0 = g_s[kc], t0 = g_t[kc];
        const float s1 = g_s[kc + 4], t1 = g_t[kc + 4];
        uint32_t bhi[4][2], blo[4][2];
        #pragma unroll
        for (int j = 0; j < 4; j++) {
            float2 pa = bp[j][kc];
            float2 pb = bp[j][kc + 4];
            bhi[j][0] = __float_as_uint(pa.x); blo[j][0] = __float_as_uint(pa.y);
            bhi[j][1] = __float_as_uint(pb.x); blo[j][1] = __float_as_uint(pb.y);
        }
        #pragma unroll
        for (int i = 0; i < 4; i++) {
            const float* p0 = in + (size_t)r0c[i] * DIN;
            const float* p1 = in + (size_t)r1c[i] * DIN;
            float v0 = fmaf(s0, p0[kc], t0);
            float v1 = fmaf(s0, p1[kc], t0);
            float v2 = fmaf(s1, p0[kc + 4], t1);
            float v3 = fmaf(s1, p1[kc + 4], t1);
            uint32_t ahi[4], alo[4];
            SPLIT(v0, ahi[0], alo[0]); SPLIT(v1, ahi[1], alo[1]);
            SPLIT(v2, ahi[2], alo[2]); SPLIT(v3, ahi[3], alo[3]);
            #pragma unroll
            for (int j = 0; j < 4; j++) {
                mma8(acc[i][j], ahi, bhi[j]);
                mma8(acc[i][j], ahi, blo[j]);
                mma8(acc[i][j], alo, bhi[j]);
            }
        }
    }

    // ---- regions 1..3: aggs (x1, x amp, x att) ----
    #pragma unroll
    for (int reg = 0; reg < 3; reg++) {
        const int kbase = DIN + reg * 4 * DIN;
        #pragma unroll 1
        for (int k0 = 0; k0 < 4 * DIN; k0 += 8) {
            const int kc = k0 + tig;
            const int kb = kbase + kc;
            uint32_t bhi[4][2], blo[4][2];
            #pragma unroll
            for (int j = 0; j < 4; j++) {
                float2 pa = bp[j][kb];
                float2 pb = bp[j][kb + 4];
                bhi[j][0] = __float_as_uint(pa.x); blo[j][0] = __float_as_uint(pa.y);
                bhi[j][1] = __float_as_uint(pb.x); blo[j][1] = __float_as_uint(pb.y);
            }
            #pragma unroll
            for (int i = 0; i < 4; i++) {
                const float sc0 = (reg == 0) ? 1.f : (reg == 1 ? amp0[i] : att0[i]);
                const float sc1 = (reg == 0) ? 1.f : (reg == 1 ? amp1[i] : att1[i]);
                const float* p0 = g_aggs + (size_t)r0c[i] * 4 * DIN;
                const float* p1 = g_aggs + (size_t)r1c[i] * 4 * DIN;
                float v0 = sc0 * p0[kc];
                float v1 = sc1 * p1[kc];
                float v2 = sc0 * p0[kc + 4];
                float v3 = sc1 * p1[kc + 4];
                uint32_t ahi[4], alo[4];
                SPLIT(v0, ahi[0], alo[0]); SPLIT(v1, ahi[1], alo[1]);
                SPLIT(v2, ahi[2], alo[2]); SPLIT(v3, ahi[3], alo[3]);
                #pragma unroll
                for (int j = 0; j < 4; j++) {
                    mma8(acc[i][j], ahi, bhi[j]);
                    mma8(acc[i][j], ahi, blo[j]);
                    mma8(acc[i][j], alo, bhi[j]);
                }
            }
        }
    }
    #undef SPLIT

    __syncthreads();  // scs/scss zeroed

    // ---- epilogue ----
    #pragma unroll
    for (int j = 0; j < 4; j++) {
        const int colj = n0 + warpN * 32 + j * 8 + tig * 2;
        const float bs0 = bias[colj], bs1 = bias[colj + 1];
        float se = 0.f, sse = 0.f, so = 0.f, sso = 0.f;
        #pragma unroll
        for (int i = 0; i < 4; i++) {
            float w00 = fmaxf(acc[i][j][0] + bs0, 0.f);
            float w01 = fmaxf(acc[i][j][1] + bs1, 0.f);
            float w10 = fmaxf(acc[i][j][2] + bs0, 0.f);
            float w11 = fmaxf(acc[i][j][3] + bs1, 0.f);
            if (r0[i] < NN) {
                *(float2*)(out + (size_t)r0[i] * DOUT + colj) = make_float2(w00, w01);
                se += w00; sse = fmaf(w00, w00, sse);
                so += w01; sso = fmaf(w01, w01, sso);
            }
            if (r1[i] < NN) {
                *(float2*)(out + (size_t)r1[i] * DOUT + colj) = make_float2(w10, w11);
                se += w10; sse = fmaf(w10, w10, sse);
                so += w11; sso = fmaf(w11, w11, sso);
            }
        }
        #pragma unroll
        for (int off = 16; off >= 4; off >>= 1) {
            se  += __shfl_xor_sync(0xffffffffu, se,  off);
            sse += __shfl_xor_sync(0xffffffffu, sse, off);
            so  += __shfl_xor_sync(0xffffffffu, so,  off);
            sso += __shfl_xor_sync(0xffffffffu, sso, off);
        }
        if (lane < 4) {
            int lc = warpN * 32 + j * 8 + lane * 2;
            atomicAdd(&scs[lc], se);
            atomicAdd(&scss[lc], sse);
            atomicAdd(&scs[lc + 1], so);
            atomicAdd(&scss[lc + 1], sso);
        }
    }
    __syncthreads();
    if (tid < 64) {
        atomicAdd(&g_colsum[n0 + tid], scs[tid]);
        atomicAdd(&g_colsumsq[n0 + tid], scss[tid]);
    }
}

__global__ void k_stats(const float* __restrict__ gamma,
                        const float* __restrict__ beta, int dout) {
    int c = blockIdx.x * blockDim.x + threadIdx.x;
    if (c >= dout) return;
    float mean = g_colsum[c] / (float)NN;
    float var = fmaxf(g_colsumsq[c] / (float)NN - mean * mean, 0.f);
    float sc = gamma[c] * rsqrtf(var + EPSW);
    g_s[c] = sc;
    g_t[c] = beta[c] - mean * sc;
}

// ==================== classifier ====================
__global__ void k_foldcls(const float* __restrict__ Wc, const float* __restrict__ bc) {
    int tid = threadIdx.x;
    if (tid < 640) {
        int c = tid / 10;
        g_wc2[tid] = g_s[c] * Wc[tid];
    }
    if (tid < 10) {
        float acc = bc[tid];
        for (int c = 0; c < 64; c++) acc = fmaf(g_t[c], Wc[c * 10 + tid], acc);
        g_bc2[tid] = acc;
    }
}
__global__ void k_cls(const float* __restrict__ r, float* __restrict__ out) {
    __shared__ float w[640];
    __shared__ float b[10];
    int tid = threadIdx.x;
    for (int i = tid; i < 640; i += blockDim.x) w[i] = g_wc2[i];
    if (tid < 10) b[tid] = g_bc2[tid];
    __syncthreads();
    int warp = (blockIdx.x * blockDim.x + tid) >> 5;
    int lane = tid & 31;
    if (warp >= NN) return;
    float v0 = r[(size_t)warp * 64 + lane];
    float v1 = r[(size_t)warp * 64 + 32 + lane];
    float acc[10];
    #pragma unroll
    for (int j = 0; j < 10; j++)
        acc[j] = v0 * w[lane * 10 + j] + v1 * w[(32 + lane) * 10 + j];
    #pragma unroll
    for (int off = 16; off; off >>= 1)
        #pragma unroll
        for (int j = 0; j < 10; j++)
            acc[j] += __shfl_xor_sync(0xffffffffu, acc[j], off);
    if (lane < 10) out[(size_t)warp * 10 + lane] = acc[lane] + b[lane];
}

// ==================== launch ====================
extern "C" void kernel_launch(void* const* d_in, const int* in_sizes, int n_in,
                              void* d_out, int out_size) {
    const float* x  = (const float*)d_in[0];
    const int*   ei = (const int*)d_in[1];
    const float* W1 = (const float*)d_in[2];
    const float* b1 = (const float*)d_in[3];
    const float* ga1 = (const float*)d_in[4];
    const float* be1 = (const float*)d_in[5];
    const float* W2 = (const float*)d_in[6];
    const float* b2 = (const float*)d_in[7];
    const float* ga2 = (const float*)d_in[8];
    const float* be2 = (const float*)d_in[9];
    const float* W3 = (const float*)d_in[10];
    const float* b3 = (const float*)d_in[11];
    const float* ga3 = (const float*)d_in[12];
    const float* be3 = (const float*)d_in[13];
    const float* W4 = (const float*)d_in[14];
    const float* b4 = (const float*)d_in[15];
    const float* ga4 = (const float*)d_in[16];
    const float* be4 = (const float*)d_in[17];
    const float* Wc = (const float*)d_in[18];
    const float* bc = (const float*)d_in[19];
    float* out = (float*)d_out;

    float *p_h0, *p_h1, *p_w1, *p_w2, *p_w3, *p_w4;
    cudaGetSymbolAddress((void**)&p_h0, g_h0);
    cudaGetSymbolAddress((void**)&p_h1, g_h1);
    cudaGetSymbolAddress((void**)&p_w1, g_wt1);
    cudaGetSymbolAddress((void**)&p_w2, g_wt2);
    cudaGetSymbolAddress((void**)&p_w3, g_wt3);
    cudaGetSymbolAddress((void**)&p_w4, g_wt4);

    // preprocessing
    k_init<<<(NN + 255) / 256, 256>>>();
    k_degcnt<<<EE / 256, 256>>>(ei);
    k_logdeg<<<(NN + 255) / 256, 256>>>();
    k_scalers<<<(NN + 255) / 256, 256>>>();
    k_scan<<<1, 1024>>>();
    k_scatter<<<EE / 256, 256>>>(ei);
    k_transpose<<<(832 * 128 + 255) / 256, 256>>>(W1, p_w1, 832, 128);
    k_transpose<<<(1664 * 256 + 255) / 256, 256>>>(W2, p_w2, 1664, 256);
    k_transpose<<<(3328 * 128 + 255) / 256, 256>>>(W3, p_w3, 3328, 128);
    k_transpose<<<(1664 * 64 + 255) / 256, 256>>>(W4, p_w4, 1664, 64);

    const int MB = (NN + 127) / 128;

    // layer 1: 64 -> 128
    k_agg<64><<<((size_t)NN * 64 + 255) / 256, 256>>>(x);
    k_zerostats<<<1, 256>>>();
    k_gemm_mma<64, 128><<<dim3(MB, 2), 128>>>(x, p_w1, b1, p_h0);
    k_stats<<<1, 256>>>(ga1, be1, 128);

    // layer 2: 128 -> 256
    k_agg<128><<<((size_t)NN * 128 + 255) / 256, 256>>>(p_h0);
    k_zerostats<<<1, 256>>>();
    k_gemm_mma<128, 256><<<dim3(MB, 4), 128>>>(p_h0, p_w2, b2, p_h1);
    k_stats<<<1, 256>>>(ga2, be2, 256);

    // layer 3: 256 -> 128
    k_agg<256><<<((size_t)NN * 256 + 255) / 256, 256>>>(p_h1);
    k_zerostats<<<1, 256>>>();
    k_gemm_mma<256, 128><<<dim3(MB, 2), 128>>>(p_h1, p_w3, b3, p_h0);
    k_stats<<<1, 256>>>(ga3, be3, 128);

    // layer 4: 128 -> 64
    k_agg<128><<<((size_t)NN * 128 + 255) / 256, 256>>>(p_h0);
    k_zerostats<<<1, 256>>>();
    k_gemm_mma<128, 64><<<dim3(MB, 1), 128>>>(p_h0, p_w4, b4, p_h1);
    k_stats<<<1, 256>>>(ga4, be4, 64);

    // classifier
    k_foldcls<<<1, 640>>>(Wc, bc);
    k_cls<<<((size_t)NN * 32 + 255) / 256, 256>>>(p_h1, out);
}

// round 7
// speedup vs baseline: 1.6203x; 1.6203x over previous
#include <cuda_runtime.h>
#include <cuda_bf16.h>
#include <math.h>
#include <stdint.h>

#define NN 50000
#define EE 800000
#define EPSW 1e-5f
#define NPAD 50048          // 782 * 64
#define NBLK16 3128         // NPAD / 16

// ---------- helpers ----------
__device__ __forceinline__ uint32_t pk2(float e0, float e1) {
    // pack: element0 -> low 16 bits, element1 -> high 16 bits
    uint32_t r;
    asm("cvt.rn.bf16x2.f32 %0, %1, %2;" : "=r"(r) : "f"(e1), "f"(e0));
    return r;
}
__device__ __forceinline__ float bfrt(float x) {   // bf16 round-trip
    return __bfloat162float(__float2bfloat16(x));
}
__device__ __forceinline__ void mma16(float* c, const uint32_t* a,
                                      uint32_t b0, uint32_t b1) {
    asm volatile("mma.sync.aligned.m16n8k16.row.col.f32.bf16.bf16.f32 "
                 "{%0,%1,%2,%3}, {%4,%5,%6,%7}, {%8,%9}, {%0,%1,%2,%3};"
                 : "+f"(c[0]), "+f"(c[1]), "+f"(c[2]), "+f"(c[3])
                 : "r"(a[0]), "r"(a[1]), "r"(a[2]), "r"(a[3]), "r"(b0), "r"(b1));
}

// ---------- scratch ----------
__device__ float g_deg[NN];
__device__ float g_logdeg[NN];
__device__ float g_amp[NN];
__device__ float g_att[NN];
__device__ float g_logsum;
__device__ int   g_rowptr[NN + 1];
__device__ int   g_cursor[NN];
__device__ int   g_col[EE];
__device__ float g_h0[(size_t)NN * 256];
__device__ float g_h1[(size_t)NN * 256];
__device__ float g_aggs[(size_t)NN * 1024];
__device__ float g_colsum[256];
__device__ float g_colsumsq[256];
__device__ float g_s[256];
__device__ float g_t[256];
__device__ float g_wc2[64 * 10];
__device__ float g_bc2[10];
// fragment-major packed operands (bf16 hi/lo)
__device__ uint4 g_packX[(size_t)NBLK16 * 16 * 32 * 2];     // up to DIN=256
__device__ uint4 g_packAgg[(size_t)NBLK16 * 64 * 32 * 2];   // up to 4*DIN=1024
__device__ uint4 g_wp1[16 * 52 * 32];
__device__ uint4 g_wp2[32 * 104 * 32];
__device__ uint4 g_wp3[16 * 208 * 32];
__device__ uint4 g_wp4[8 * 104 * 32];

// ---------- preprocessing ----------
__global__ void k_init() {
    int i = blockIdx.x * blockDim.x + threadIdx.x;
    if (i < NN) g_deg[i] = 0.f;
    if (i < 256) { g_s[i] = 1.f; g_t[i] = 0.f; }
    if (i == 0) g_logsum = 0.f;
}
__global__ void k_degcnt(const int* __restrict__ ei) {
    int e = blockIdx.x * blockDim.x + threadIdx.x;
    if (e < EE) atomicAdd(&g_deg[ei[EE + e]], 1.f);
}
__global__ void k_logdeg() {
    int n = blockIdx.x * blockDim.x + threadIdx.x;
    float ld = 0.f;
    if (n < NN) { ld = log1pf(g_deg[n]); g_logdeg[n] = ld; }
    __shared__ float sh[256];
    sh[threadIdx.x] = ld;
    __syncthreads();
    for (int off = 128; off; off >>= 1) {
        if (threadIdx.x < off) sh[threadIdx.x] += sh[threadIdx.x + off];
        __syncthreads();
    }
    if (threadIdx.x == 0) atomicAdd(&g_logsum, sh[0]);
}
// scan + scaler computation
__global__ void k_scan() {
    __shared__ int wsum[32];
    __shared__ int carry_s;
    int tid = threadIdx.x, lane = tid & 31, wid = tid >> 5;
    float delta = g_logsum / (float)NN;
    if (tid == 0) carry_s = 0;
    __syncthreads();
    for (int base = 0; base < NN; base += 1024) {
        int i = base + tid;
        int v = 0;
        if (i < NN) {
            v = (int)g_deg[i];
            float ld = g_logdeg[i];
            g_amp[i] = ld / delta;
            g_att[i] = (ld > 0.f) ? delta / fmaxf(ld, 1e-6f) : 1.f;
        }
        int x = v;
        #pragma unroll
        for (int off = 1; off < 32; off <<= 1) {
            int y = __shfl_up_sync(0xffffffffu, x, off);
            if (lane >= off) x += y;
        }
        if (lane == 31) wsum[wid] = x;
        __syncthreads();
        if (wid == 0) {
            int w = wsum[lane];
            #pragma unroll
            for (int off = 1; off < 32; off <<= 1) {
                int y = __shfl_up_sync(0xffffffffu, w, off);
                if (lane >= off) w += y;
            }
            wsum[lane] = w;
        }
        __syncthreads();
        int incl = x + (wid > 0 ? wsum[wid - 1] : 0);
        int carry = carry_s;
        if (i < NN) { g_rowptr[i] = carry + incl - v; g_cursor[i] = carry + incl - v; }
        __syncthreads();
        if (tid == 1023) carry_s = carry + incl;
        __syncthreads();
    }
    if (tid == 0) g_rowptr[NN] = carry_s;
}
__global__ void k_scatter(const int* __restrict__ ei) {
    int e = blockIdx.x * blockDim.x + threadIdx.x;
    if (e >= EE) return;
    int dst = ei[EE + e];
    int pos = atomicAdd(&g_cursor[dst], 1);
    g_col[pos] = ei[e];
}

// pack weights: per (nblk, kblk, lane): uint4 = {bhi0, bhi1, blo0, blo1}
__global__ void k_packW(const float* __restrict__ W, uint4* __restrict__ dst,
                        int K13, int DOUT) {
    int KBW = K13 / 16;
    int total = (DOUT / 8) * KBW * 32;
    int t = blockIdx.x * blockDim.x + threadIdx.x;
    if (t >= total) return;
    int lane = t & 31;
    int kb = (t >> 5) % KBW;
    int nblk = (t >> 5) / KBW;
    int gr = lane >> 2, tig = lane & 3;
    int n = nblk * 8 + gr;
    int k0 = kb * 16 + tig * 2;
    float w00 = W[(size_t)k0 * DOUT + n];
    float w01 = W[(size_t)(k0 + 1) * DOUT + n];
    float w80 = W[(size_t)(k0 + 8) * DOUT + n];
    float w81 = W[(size_t)(k0 + 9) * DOUT + n];
    uint4 o;
    o.x = pk2(w00, w01);
    o.y = pk2(w80, w81);
    o.z = pk2(w00 - bfrt(w00), w01 - bfrt(w01));
    o.w = pk2(w80 - bfrt(w80), w81 - bfrt(w81));
    dst[t] = o;
}

// pack activations to fragment-major hi/lo.
// grid (NBLK16, D/64), 128 thr. mode=1: apply BN affine g_s/g_t.
__global__ void k_packA(const float* __restrict__ src, uint4* __restrict__ dst,
                        int D, int mode) {
    __shared__ float sm[16][64];
    int tid = threadIdx.x;
    int gy = blockIdx.y * 64;
    #pragma unroll
    for (int tt = tid; tt < 256; tt += 128) {
        int row = tt >> 4, c4 = (tt & 15) * 4;
        int m = blockIdx.x * 16 + row;
        if (m >= NN) m = NN - 1;
        *(float4*)&sm[row][c4] = *(const float4*)(src + (size_t)m * D + gy + c4);
    }
    __syncthreads();
    int kb = tid >> 5, lane = tid & 31;
    int gr = lane >> 2, tig = lane & 3;
    int c0 = kb * 16 + tig * 2;
    float v[8];
    #pragma unroll
    for (int h = 0; h < 2; h++) {        // k-half: +0 / +8
        int c = c0 + h * 8;
        float s0 = 1.f, t0 = 0.f, s1 = 1.f, t1 = 0.f;
        if (mode) { s0 = g_s[gy + c]; t0 = g_t[gy + c];
                    s1 = g_s[gy + c + 1]; t1 = g_t[gy + c + 1]; }
        v[h * 4 + 0] = fmaf(s0, sm[gr][c], t0);
        v[h * 4 + 1] = fmaf(s1, sm[gr][c + 1], t1);
        v[h * 4 + 2] = fmaf(s0, sm[gr + 8][c], t0);
        v[h * 4 + 3] = fmaf(s1, sm[gr + 8][c + 1], t1);
    }
    uint4 hi, lo;
    hi.x = pk2(v[0], v[1]);
    hi.y = pk2(v[2], v[3]);
    hi.z = pk2(v[4], v[5]);
    hi.w = pk2(v[6], v[7]);
    lo.x = pk2(v[0] - bfrt(v[0]), v[1] - bfrt(v[1]));
    lo.y = pk2(v[2] - bfrt(v[2]), v[3] - bfrt(v[3]));
    lo.z = pk2(v[4] - bfrt(v[4]), v[5] - bfrt(v[5]));
    lo.w = pk2(v[6] - bfrt(v[6]), v[7] - bfrt(v[7]));
    int KB = D / 16;
    size_t idx = (((size_t)blockIdx.x * KB + (blockIdx.y * 4 + kb)) * 32 + lane) * 2;
    dst[idx] = hi;
    dst[idx + 1] = lo;
}

// ---------- aggregation ----------
template <int DIN>
__global__ void k_agg(const float* __restrict__ in) {
    const int CH = DIN / 32;
    int warp = (blockIdx.x * blockDim.x + threadIdx.x) >> 5;
    int lane = threadIdx.x & 31;
    if (warp >= NN * CH) return;
    int n = warp / CH;
    int c = (warp % CH) * 32 + lane;
    float s = g_s[c], t = g_t[c];
    int beg = g_rowptr[n], end = g_rowptr[n + 1];
    float sum = 0.f, ss = 0.f, mn = INFINITY, mx = -INFINITY;
    for (int j = beg; j < end; j++) {
        int src = g_col[j];
        float v = in[(size_t)src * DIN + c];
        v = fmaf(s, v, t);
        sum += v; ss = fmaf(v, v, ss);
        mn = fminf(mn, v); mx = fmaxf(mx, v);
    }
    float deg = (float)(end - beg);
    float cnt = fmaxf(deg, 1.f);
    float mean = sum / cnt;
    float var = fmaxf(ss / cnt - mean * mean, 0.f);
    float sd = sqrtf(var + EPSW);
    bool has = end > beg;
    mn = has ? mn : 0.f;
    mx = has ? mx : 0.f;
    float* ag = g_aggs + (size_t)n * 4 * DIN;
    ag[c] = mean;
    ag[DIN + c] = mn;
    ag[2 * DIN + c] = mx;
    ag[3 * DIN + c] = sd;
}
__global__ void k_zerostats() {
    int c = threadIdx.x;
    if (c < 256) { g_colsum[c] = 0.f; g_colsumsq[c] = 0.f; }
}

// ---------- bf16x2 3-pass fused PNA GEMM ----------
template <int DIN, int DOUT>
__global__ void __launch_bounds__(128) k_gemm_bf(const uint4* __restrict__ pX,
                                                 const uint4* __restrict__ pA,
                                                 const uint4* __restrict__ pW,
                                                 const float* __restrict__ bias,
                                                 float* __restrict__ out) {
    constexpr int KBX = DIN / 16;
    constexpr int KBA = DIN / 4;
    constexpr int KBW = 13 * DIN / 16;
    __shared__ float scs[64], scss[64];
    const int tid = threadIdx.x, lane = tid & 31, wid = tid >> 5;
    const int warpM = wid & 1, warpN = wid >> 1;
    const int gr = lane >> 2, tig = lane & 3;
    const int mblk0 = blockIdx.x * 4 + warpM * 2;
    const int nblk0 = blockIdx.y * 8 + warpN * 4;

    if (tid < 64) { scs[tid] = 0.f; scss[tid] = 0.f; }

    float acc[3][2][4][4];
    #pragma unroll
    for (int s = 0; s < 3; s++)
        #pragma unroll
        for (int i = 0; i < 2; i++)
            #pragma unroll
            for (int j = 0; j < 4; j++)
                #pragma unroll
                for (int q = 0; q < 4; q++) acc[s][i][j][q] = 0.f;

    // ---- x region ----
    #pragma unroll 1
    for (int kb = 0; kb < KBX; kb++) {
        uint4 ah[2], al[2];
        #pragma unroll
        for (int i = 0; i < 2; i++) {
            size_t ai = (((size_t)(mblk0 + i) * KBX + kb) * 32 + lane) * 2;
            ah[i] = pX[ai]; al[i] = pX[ai + 1];
        }
        #pragma unroll
        for (int j = 0; j < 4; j++) {
            uint4 b = pW[((size_t)(nblk0 + j) * KBW + kb) * 32 + lane];
            #pragma unroll
            for (int i = 0; i < 2; i++) {
                mma16(acc[0][i][j], (const uint32_t*)&ah[i], b.x, b.y);
                mma16(acc[0][i][j], (const uint32_t*)&ah[i], b.z, b.w);
                mma16(acc[0][i][j], (const uint32_t*)&al[i], b.x, b.y);
            }
        }
    }
    // ---- aggs region: 3 weight streams ----
    #pragma unroll 1
    for (int kb = 0; kb < KBA; kb++) {
        uint4 ah[2], al[2];
        #pragma unroll
        for (int i = 0; i < 2; i++) {
            size_t ai = (((size_t)(mblk0 + i) * KBA + kb) * 32 + lane) * 2;
            ah[i] = pA[ai]; al[i] = pA[ai + 1];
        }
        #pragma unroll
        for (int s = 0; s < 3; s++) {
            const int kbg = KBX + s * KBA + kb;
            #pragma unroll
            for (int j = 0; j < 4; j++) {
                uint4 b = pW[((size_t)(nblk0 + j) * KBW + kbg) * 32 + lane];
                #pragma unroll
                for (int i = 0; i < 2; i++) {
                    mma16(acc[s][i][j], (const uint32_t*)&ah[i], b.x, b.y);
                    mma16(acc[s][i][j], (const uint32_t*)&ah[i], b.z, b.w);
                    mma16(acc[s][i][j], (const uint32_t*)&al[i], b.x, b.y);
                }
            }
        }
    }
    __syncthreads();

    // ---- epilogue ----
    const int m0w = blockIdx.x * 64 + warpM * 32;
    const int n0w = blockIdx.y * 64 + warpN * 32;
    float ampv[2][2], attv[2][2];
    #pragma unroll
    for (int i = 0; i < 2; i++) {
        int ra = m0w + i * 16 + gr, rb = ra + 8;
        int rac = ra < NN ? ra : NN - 1, rbc = rb < NN ? rb : NN - 1;
        ampv[i][0] = g_amp[rac]; ampv[i][1] = g_amp[rbc];
        attv[i][0] = g_att[rac]; attv[i][1] = g_att[rbc];
    }
    #pragma unroll
    for (int j = 0; j < 4; j++) {
        const int col = n0w + j * 8 + tig * 2;
        const float bs0 = bias[col], bs1 = bias[col + 1];
        float cs0 = 0.f, css0 = 0.f, cs1 = 0.f, css1 = 0.f;
        #pragma unroll
        for (int i = 0; i < 2; i++) {
            int ra = m0w + i * 16 + gr, rb = ra + 8;
            float v00 = fmaxf(acc[0][i][j][0] + ampv[i][0] * acc[1][i][j][0] +
                              attv[i][0] * acc[2][i][j][0] + bs0, 0.f);
            float v01 = fmaxf(acc[0][i][j][1] + ampv[i][0] * acc[1][i][j][1] +
                              attv[i][0] * acc[2][i][j][1] + bs1, 0.f);
            float v10 = fmaxf(acc[0][i][j][2] + ampv[i][1] * acc[1][i][j][2] +
                              attv[i][1] * acc[2][i][j][2] + bs0, 0.f);
            float v11 = fmaxf(acc[0][i][j][3] + ampv[i][1] * acc[1][i][j][3] +
                              attv[i][1] * acc[2][i][j][3] + bs1, 0.f);
            if (ra < NN) {
                *(float2*)(out + (size_t)ra * DOUT + col) = make_float2(v00, v01);
                cs0 += v00; css0 = fmaf(v00, v00, css0);
                cs1 += v01; css1 = fmaf(v01, v01, css1);
            }
            if (rb < NN) {
                *(float2*)(out + (size_t)rb * DOUT + col) = make_float2(v10, v11);
                cs0 += v10; css0 = fmaf(v10, v10, css0);
                cs1 += v11; css1 = fmaf(v11, v11, css1);
            }
        }
        #pragma unroll
        for (int off = 16; off >= 4; off >>= 1) {
            cs0 += __shfl_xor_sync(0xffffffffu, cs0, off);
            css0 += __shfl_xor_sync(0xffffffffu, css0, off);
            cs1 += __shfl_xor_sync(0xffffffffu, cs1, off);
            css1 += __shfl_xor_sync(0xffffffffu, css1, off);
        }
        if (gr == 0) {
            int lc = warpN * 32 + j * 8 + tig * 2;
            atomicAdd(&scs[lc], cs0);
            atomicAdd(&scss[lc], css0);
            atomicAdd(&scs[lc + 1], cs1);
            atomicAdd(&scss[lc + 1], css1);
        }
    }
    __syncthreads();
    if (tid < 64) {
        atomicAdd(&g_colsum[blockIdx.y * 64 + tid], scs[tid]);
        atomicAdd(&g_colsumsq[blockIdx.y * 64 + tid], scss[tid]);
    }
}

__global__ void k_stats(const float* __restrict__ gamma,
                        const float* __restrict__ beta, int dout) {
    int c = blockIdx.x * blockDim.x + threadIdx.x;
    if (c >= dout) return;
    float mean = g_colsum[c] / (float)NN;
    float var = fmaxf(g_colsumsq[c] / (float)NN - mean * mean, 0.f);
    float sc = gamma[c] * rsqrtf(var + EPSW);
    g_s[c] = sc;
    g_t[c] = beta[c] - mean * sc;
}

// ---------- classifier ----------
__global__ void k_foldcls(const float* __restrict__ Wc, const float* __restrict__ bc) {
    int tid = threadIdx.x;
    if (tid < 640) {
        int c = tid / 10;
        g_wc2[tid] = g_s[c] * Wc[tid];
    }
    if (tid < 10) {
        float acc = bc[tid];
        for (int c = 0; c < 64; c++) acc = fmaf(g_t[c], Wc[c * 10 + tid], acc);
        g_bc2[tid] = acc;
    }
}
__global__ void k_cls(const float* __restrict__ r, float* __restrict__ out) {
    __shared__ float w[640];
    __shared__ float b[10];
    int tid = threadIdx.x;
    for (int i = tid; i < 640; i += blockDim.x) w[i] = g_wc2[i];
    if (tid < 10) b[tid] = g_bc2[tid];
    __syncthreads();
    int warp = (blockIdx.x * blockDim.x + tid) >> 5;
    int lane = tid & 31;
    if (warp >= NN) return;
    float v0 = r[(size_t)warp * 64 + lane];
    float v1 = r[(size_t)warp * 64 + 32 + lane];
    float acc[10];
    #pragma unroll
    for (int j = 0; j < 10; j++)
        acc[j] = v0 * w[lane * 10 + j] + v1 * w[(32 + lane) * 10 + j];
    #pragma unroll
    for (int off = 16; off; off >>= 1)
        #pragma unroll
        for (int j = 0; j < 10; j++)
            acc[j] += __shfl_xor_sync(0xffffffffu, acc[j], off);
    if (lane < 10) out[(size_t)warp * 10 + lane] = acc[lane] + b[lane];
}

// ---------- launch ----------
extern "C" void kernel_launch(void* const* d_in, const int* in_sizes, int n_in,
                              void* d_out, int out_size) {
    const float* x  = (const float*)d_in[0];
    const int*   ei = (const int*)d_in[1];
    const float* W1 = (const float*)d_in[2];
    const float* b1 = (const float*)d_in[3];
    const float* ga1 = (const float*)d_in[4];
    const float* be1 = (const float*)d_in[5];
    const float* W2 = (const float*)d_in[6];
    const float* b2 = (const float*)d_in[7];
    const float* ga2 = (const float*)d_in[8];
    const float* be2 = (const float*)d_in[9];
    const float* W3 = (const float*)d_in[10];
    const float* b3 = (const float*)d_in[11];
    const float* ga3 = (const float*)d_in[12];
    const float* be3 = (const float*)d_in[13];
    const float* W4 = (const float*)d_in[14];
    const float* b4 = (const float*)d_in[15];
    const float* ga4 = (const float*)d_in[16];
    const float* be4 = (const float*)d_in[17];
    const float* Wc = (const float*)d_in[18];
    const float* bc = (const float*)d_in[19];
    float* out = (float*)d_out;

    float *p_h0, *p_h1, *p_aggs;
    uint4 *pX, *pA, *pw1, *pw2, *pw3, *pw4;
    cudaGetSymbolAddress((void**)&p_h0, g_h0);
    cudaGetSymbolAddress((void**)&p_h1, g_h1);
    cudaGetSymbolAddress((void**)&p_aggs, g_aggs);   // FIX: device address, not host shadow
    cudaGetSymbolAddress((void**)&pX, g_packX);
    cudaGetSymbolAddress((void**)&pA, g_packAgg);
    cudaGetSymbolAddress((void**)&pw1, g_wp1);
    cudaGetSymbolAddress((void**)&pw2, g_wp2);
    cudaGetSymbolAddress((void**)&pw3, g_wp3);
    cudaGetSymbolAddress((void**)&pw4, g_wp4);

    // preprocessing (slots 0-4), slot 5 = k_agg<64> for the ncu window
    k_init<<<(NN + 255) / 256, 256>>>();
    k_degcnt<<<EE / 256, 256>>>(ei);
    k_logdeg<<<(NN + 255) / 256, 256>>>();
    k_scan<<<1, 1024>>>();
    k_scatter<<<EE / 256, 256>>>(ei);

    // ---- layer 1: 64 -> 128 ----
    k_agg<64><<<((size_t)NN * 64 + 255) / 256, 256>>>(x);
    k_packW<<<(16 * 52 * 32 + 255) / 256, 256>>>(W1, pw1, 832, 128);
    k_packW<<<(32 * 104 * 32 + 255) / 256, 256>>>(W2, pw2, 1664, 256);
    k_packW<<<(16 * 208 * 32 + 255) / 256, 256>>>(W3, pw3, 3328, 128);
    k_packW<<<(8 * 104 * 32 + 255) / 256, 256>>>(W4, pw4, 1664, 64);
    k_packA<<<dim3(NBLK16, 1), 128>>>(x, pX, 64, 1);
    k_packA<<<dim3(NBLK16, 4), 128>>>(p_aggs, pA, 256, 0);
    k_zerostats<<<1, 256>>>();
    k_gemm_bf<64, 128><<<dim3(NPAD / 64, 2), 128>>>(pX, pA, pw1, b1, p_h0);
    k_stats<<<1, 256>>>(ga1, be1, 128);

    // ---- layer 2: 128 -> 256 ----
    k_agg<128><<<((size_t)NN * 128 + 255) / 256, 256>>>(p_h0);
    k_packA<<<dim3(NBLK16, 2), 128>>>(p_h0, pX, 128, 1);
    k_packA<<<dim3(NBLK16, 8), 128>>>(p_aggs, pA, 512, 0);
    k_zerostats<<<1, 256>>>();
    k_gemm_bf<128, 256><<<dim3(NPAD / 64, 4), 128>>>(pX, pA, pw2, b2, p_h1);
    k_stats<<<1, 256>>>(ga2, be2, 256);

    // ---- layer 3: 256 -> 128 ----
    k_agg<256><<<((size_t)NN * 256 + 255) / 256, 256>>>(p_h1);
    k_packA<<<dim3(NBLK16, 4), 128>>>(p_h1, pX, 256, 1);
    k_packA<<<dim3(NBLK16, 16), 128>>>(p_aggs, pA, 1024, 0);
    k_zerostats<<<1, 256>>>();
    k_gemm_bf<256, 128><<<dim3(NPAD / 64, 2), 128>>>(pX, pA, pw3, b3, p_h0);
    k_stats<<<1, 256>>>(ga3, be3, 128);

    // ---- layer 4: 128 -> 64 ----
    k_agg<128><<<((size_t)NN * 128 + 255) / 256, 256>>>(p_h0);
    k_packA<<<dim3(NBLK16, 2), 128>>>(p_h0, pX, 128, 1);
    k_packA<<<dim3(NBLK16, 8), 128>>>(p_aggs, pA, 512, 0);
    k_zerostats<<<1, 256>>>();
    k_gemm_bf<128, 64><<<dim3(NPAD / 64, 1), 128>>>(pX, pA, pw4, b4, p_h1);
    k_stats<<<1, 256>>>(ga4, be4, 64);

    // ---- classifier ----
    k_foldcls<<<1, 640>>>(Wc, bc);
    k_cls<<<((size_t)NN * 32 + 255) / 256, 256>>>(p_h1, out);
}

// round 8
// speedup vs baseline: 1.7639x; 1.0886x over previous
#include <cuda_runtime.h>
#include <cuda_bf16.h>
#include <math.h>
#include <stdint.h>

#define NN 50000
#define EE 800000
#define EPSW 1e-5f
#define NPAD 50048          // 782 * 64
#define NBLK16 3128         // NPAD / 16
#define SCAN_BLOCKS 49      // ceil(NN / 1024)

// ---------- helpers ----------
__device__ __forceinline__ uint32_t pk2(float e0, float e1) {
    uint32_t r;
    asm("cvt.rn.bf16x2.f32 %0, %1, %2;" : "=r"(r) : "f"(e1), "f"(e0));
    return r;
}
__device__ __forceinline__ float bfrt(float x) {
    return __bfloat162float(__float2bfloat16(x));
}
__device__ __forceinline__ void mma16(float* c, const uint32_t* a,
                                      uint32_t b0, uint32_t b1) {
    asm volatile("mma.sync.aligned.m16n8k16.row.col.f32.bf16.bf16.f32 "
                 "{%0,%1,%2,%3}, {%4,%5,%6,%7}, {%8,%9}, {%0,%1,%2,%3};"
                 : "+f"(c[0]), "+f"(c[1]), "+f"(c[2]), "+f"(c[3])
                 : "r"(a[0]), "r"(a[1]), "r"(a[2]), "r"(a[3]), "r"(b0), "r"(b1));
}

// ---------- scratch ----------
__device__ float g_deg[NN];
__device__ float g_logdeg[NN];
__device__ float g_amp[NN];
__device__ float g_att[NN];
__device__ float g_logsum;
__device__ int   g_rowptr[NN + 1];
__device__ int   g_cursor[NN];
__device__ int   g_col[EE];
__device__ float g_h0[(size_t)NN * 256];
__device__ float g_h1[(size_t)NN * 256];
__device__ float g_colsum[256];
__device__ float g_colsumsq[256];
__device__ float g_s[256];
__device__ float g_t[256];
__device__ float g_wc2[64 * 10];
__device__ float g_bc2[10];
__device__ int   g_bsum[64];
__device__ int   g_bpre[64];
__device__ int   g_bflag[64];
// fragment-major packed operands (bf16 hi/lo)
__device__ uint4 g_packX[(size_t)NBLK16 * 16 * 32 * 2];     // up to DIN=256
__device__ uint4 g_packAgg[(size_t)NBLK16 * 64 * 32 * 2];   // up to 4*DIN=1024
__device__ uint4 g_wp1[16 * 52 * 32];
__device__ uint4 g_wp2[32 * 104 * 32];
__device__ uint4 g_wp3[16 * 208 * 32];
__device__ uint4 g_wp4[8 * 104 * 32];

// ---------- preprocessing ----------
__global__ void k_init() {
    int i = blockIdx.x * blockDim.x + threadIdx.x;
    if (i < NN) g_deg[i] = 0.f;
    if (i < 256) { g_s[i] = 1.f; g_t[i] = 0.f; g_colsum[i] = 0.f; g_colsumsq[i] = 0.f; }
    if (i < 64) g_bflag[i] = 0;
    if (i == 0) g_logsum = 0.f;
}
__global__ void k_degcnt(const int* __restrict__ ei) {
    int e = blockIdx.x * blockDim.x + threadIdx.x;
    if (e < EE) atomicAdd(&g_deg[ei[EE + e]], 1.f);
}
__global__ void k_logdeg() {
    int n = blockIdx.x * blockDim.x + threadIdx.x;
    float ld = 0.f;
    if (n < NN) { ld = log1pf(g_deg[n]); g_logdeg[n] = ld; }
    __shared__ float sh[256];
    sh[threadIdx.x] = ld;
    __syncthreads();
    for (int off = 128; off; off >>= 1) {
        if (threadIdx.x < off) sh[threadIdx.x] += sh[threadIdx.x + off];
        __syncthreads();
    }
    if (threadIdx.x == 0) atomicAdd(&g_logsum, sh[0]);
}
// multi-block exclusive scan with decoupled lookback; also computes amp/att
__global__ void k_scan2() {
    __shared__ int wsum[32];
    __shared__ int s_off;
    const int tid = threadIdx.x, lane = tid & 31, wid = tid >> 5;
    const int bid = blockIdx.x;
    const int i = bid * 1024 + tid;
    const float delta = g_logsum / (float)NN;
    int v = 0;
    if (i < NN) {
        v = (int)g_deg[i];
        float ld = g_logdeg[i];
        g_amp[i] = ld / delta;
        g_att[i] = (ld > 0.f) ? delta / fmaxf(ld, 1e-6f) : 1.f;
    }
    int x = v;
    #pragma unroll
    for (int off = 1; off < 32; off <<= 1) {
        int y = __shfl_up_sync(0xffffffffu, x, off);
        if (lane >= off) x += y;
    }
    if (lane == 31) wsum[wid] = x;
    __syncthreads();
    if (wid == 0) {
        int w = wsum[lane];
        #pragma unroll
        for (int off = 1; off < 32; off <<= 1) {
            int y = __shfl_up_sync(0xffffffffu, w, off);
            if (lane >= off) w += y;
        }
        wsum[lane] = w;
    }
    __syncthreads();
    const int incl = x + (wid > 0 ? wsum[wid - 1] : 0);
    // publish block aggregate ASAP
    if (tid == 1023) {
        g_bsum[bid] = incl;
        __threadfence();
        if (bid == 0) {
            g_bpre[0] = incl;
            __threadfence();
            atomicExch(&g_bflag[0], 2);
        } else {
            atomicExch(&g_bflag[bid], 1);
        }
    }
    // lookback
    if (tid == 0) {
        int off = 0;
        if (bid > 0) {
            int p = bid - 1;
            while (p >= 0) {
                int f;
                do { f = atomicAdd(&g_bflag[p], 0); } while (f == 0);
                if (f == 2) { off += atomicAdd(&g_bpre[p], 0); break; }
                off += atomicAdd(&g_bsum[p], 0);
                p--;
            }
        }
        s_off = off;
    }
    __syncthreads();
    const int off = s_off;
    if (i < NN) {
        int ex = off + incl - v;
        g_rowptr[i] = ex;
        g_cursor[i] = ex;
        if (i == NN - 1) g_rowptr[NN] = off + incl;
    }
    if (tid == 1023 && bid > 0) {
        g_bpre[bid] = off + incl;
        __threadfence();
        atomicExch(&g_bflag[bid], 2);
    }
}
__global__ void k_scatter(const int* __restrict__ ei) {
    int e = blockIdx.x * blockDim.x + threadIdx.x;
    if (e >= EE) return;
    int dst = ei[EE + e];
    int pos = atomicAdd(&g_cursor[dst], 1);
    g_col[pos] = ei[e];
}

// pack weights: per (nblk, kblk, lane): uint4 = {bhi0, bhi1, blo0, blo1}
__global__ void k_packW(const float* __restrict__ W, uint4* __restrict__ dst,
                        int K13, int DOUT) {
    int KBW = K13 / 16;
    int total = (DOUT / 8) * KBW * 32;
    int t = blockIdx.x * blockDim.x + threadIdx.x;
    if (t >= total) return;
    int lane = t & 31;
    int kb = (t >> 5) % KBW;
    int nblk = (t >> 5) / KBW;
    int gr = lane >> 2, tig = lane & 3;
    int n = nblk * 8 + gr;
    int k0 = kb * 16 + tig * 2;
    float w00 = W[(size_t)k0 * DOUT + n];
    float w01 = W[(size_t)(k0 + 1) * DOUT + n];
    float w80 = W[(size_t)(k0 + 8) * DOUT + n];
    float w81 = W[(size_t)(k0 + 9) * DOUT + n];
    uint4 o;
    o.x = pk2(w00, w01);
    o.y = pk2(w80, w81);
    o.z = pk2(w00 - bfrt(w00), w01 - bfrt(w01));
    o.w = pk2(w80 - bfrt(w80), w81 - bfrt(w81));
    dst[t] = o;
}

// pack X activations (with BN affine) to fragment-major hi/lo.
__global__ void k_packA(const float* __restrict__ src, uint4* __restrict__ dst,
                        int D) {
    __shared__ float sm[16][64];
    int tid = threadIdx.x;
    int gy = blockIdx.y * 64;
    #pragma unroll
    for (int tt = tid; tt < 256; tt += 128) {
        int row = tt >> 4, c4 = (tt & 15) * 4;
        int m = blockIdx.x * 16 + row;
        if (m >= NN) m = NN - 1;
        *(float4*)&sm[row][c4] = *(const float4*)(src + (size_t)m * D + gy + c4);
    }
    __syncthreads();
    int kb = tid >> 5, lane = tid & 31;
    int gr = lane >> 2, tig = lane & 3;
    int c0 = kb * 16 + tig * 2;
    float v[8];
    #pragma unroll
    for (int h = 0; h < 2; h++) {
        int c = c0 + h * 8;
        float s0 = g_s[gy + c], t0 = g_t[gy + c];
        float s1 = g_s[gy + c + 1], t1 = g_t[gy + c + 1];
        v[h * 4 + 0] = fmaf(s0, sm[gr][c], t0);
        v[h * 4 + 1] = fmaf(s1, sm[gr][c + 1], t1);
        v[h * 4 + 2] = fmaf(s0, sm[gr + 8][c], t0);
        v[h * 4 + 3] = fmaf(s1, sm[gr + 8][c + 1], t1);
    }
    uint4 hi, lo;
    hi.x = pk2(v[0], v[1]);
    hi.y = pk2(v[2], v[3]);
    hi.z = pk2(v[4], v[5]);
    hi.w = pk2(v[6], v[7]);
    lo.x = pk2(v[0] - bfrt(v[0]), v[1] - bfrt(v[1]));
    lo.y = pk2(v[2] - bfrt(v[2]), v[3] - bfrt(v[3]));
    lo.z = pk2(v[4] - bfrt(v[4]), v[5] - bfrt(v[5]));
    lo.w = pk2(v[6] - bfrt(v[6]), v[7] - bfrt(v[7]));
    int KB = D / 16;
    size_t idx = (((size_t)blockIdx.x * KB + (blockIdx.y * 4 + kb)) * 32 + lane) * 2;
    dst[idx] = hi;
    dst[idx + 1] = lo;
}

// ---------- fused aggregation + fragment pack ----------
// CTA: 256 thr, 16 nodes x 32-channel slab. Each warp aggregates 2 nodes,
// stages [mean|min|max|std] in smem, then packs 8 (16x16) fragment blocks
// of the virtual aggs matrix straight to bf16 hi/lo — fp32 aggs never exists.
template <int DIN>
__global__ void __launch_bounds__(256) k_aggp(const float* __restrict__ in,
                                              uint4* __restrict__ pA) {
    constexpr int KBA = DIN / 4;       // total k-blocks of [N, 4*DIN]
    __shared__ float sm[16][4][33];
    const int tid = threadIdx.x, lane = tid & 31, w = tid >> 5;
    const int nb = blockIdx.x * 16;
    const int c = blockIdx.y * 32 + lane;
    const float s = g_s[c], t = g_t[c];
    #pragma unroll
    for (int u = 0; u < 2; u++) {
        int nloc = w * 2 + u;
        int n = nb + nloc; if (n >= NN) n = NN - 1;
        int beg = g_rowptr[n], end = g_rowptr[n + 1];
        float sum = 0.f, ss = 0.f, mn = INFINITY, mx = -INFINITY;
        for (int j = beg; j < end; j++) {
            int src = g_col[j];
            float v = fmaf(s, in[(size_t)src * DIN + c], t);
            sum += v; ss = fmaf(v, v, ss);
            mn = fminf(mn, v); mx = fmaxf(mx, v);
        }
        float deg = (float)(end - beg);
        float cnt = fmaxf(deg, 1.f);
        float mean = sum / cnt;
        float var = fmaxf(ss / cnt - mean * mean, 0.f);
        float sd = sqrtf(var + EPSW);
        bool has = end > beg;
        sm[nloc][0][lane] = mean;
        sm[nloc][1][lane] = has ? mn : 0.f;
        sm[nloc][2][lane] = has ? mx : 0.f;
        sm[nloc][3][lane] = sd;
    }
    __syncthreads();
    // pack: warp w -> aggregator a = w>>1, 16-col half h = w&1
    const int a = w >> 1, h = w & 1;
    const int gr = lane >> 2, tig = lane & 3;
    const int t2 = h * 16 + tig * 2;
    float v0 = sm[gr][a][t2],         v1 = sm[gr][a][t2 + 1];
    float v2 = sm[gr + 8][a][t2],     v3 = sm[gr + 8][a][t2 + 1];
    float v4 = sm[gr][a][t2 + 8],     v5 = sm[gr][a][t2 + 9];
    float v6 = sm[gr + 8][a][t2 + 8], v7 = sm[gr + 8][a][t2 + 9];
    uint4 hi, lo;
    hi.x = pk2(v0, v1); hi.y = pk2(v2, v3);
    hi.z = pk2(v4, v5); hi.w = pk2(v6, v7);
    lo.x = pk2(v0 - bfrt(v0), v1 - bfrt(v1));
    lo.y = pk2(v2 - bfrt(v2), v3 - bfrt(v3));
    lo.z = pk2(v4 - bfrt(v4), v5 - bfrt(v5));
    lo.w = pk2(v6 - bfrt(v6), v7 - bfrt(v7));
    const int kb = a * (DIN / 16) + blockIdx.y * 2 + h;
    size_t idx = (((size_t)blockIdx.x * KBA + kb) * 32 + lane) * 2;
    pA[idx] = hi;
    pA[idx + 1] = lo;
}

// ---------- bf16x2 3-pass fused PNA GEMM ----------
template <int DIN, int DOUT>
__global__ void __launch_bounds__(128) k_gemm_bf(const uint4* __restrict__ pX,
                                                 const uint4* __restrict__ pA,
                                                 const uint4* __restrict__ pW,
                                                 const float* __restrict__ bias,
                                                 float* __restrict__ out) {
    constexpr int KBX = DIN / 16;
    constexpr int KBA = DIN / 4;
    constexpr int KBW = 13 * DIN / 16;
    __shared__ float scs[64], scss[64];
    const int tid = threadIdx.x, lane = tid & 31, wid = tid >> 5;
    const int warpM = wid & 1, warpN = wid >> 1;
    const int gr = lane >> 2, tig = lane & 3;
    const int mblk0 = blockIdx.x * 4 + warpM * 2;
    const int nblk0 = blockIdx.y * 8 + warpN * 4;

    if (tid < 64) { scs[tid] = 0.f; scss[tid] = 0.f; }

    float acc[3][2][4][4];
    #pragma unroll
    for (int s = 0; s < 3; s++)
        #pragma unroll
        for (int i = 0; i < 2; i++)
            #pragma unroll
            for (int j = 0; j < 4; j++)
                #pragma unroll
                for (int q = 0; q < 4; q++) acc[s][i][j][q] = 0.f;

    // ---- x region ----
    #pragma unroll 1
    for (int kb = 0; kb < KBX; kb++) {
        uint4 ah[2], al[2];
        #pragma unroll
        for (int i = 0; i < 2; i++) {
            size_t ai = (((size_t)(mblk0 + i) * KBX + kb) * 32 + lane) * 2;
            ah[i] = pX[ai]; al[i] = pX[ai + 1];
        }
        #pragma unroll
        for (int j = 0; j < 4; j++) {
            uint4 b = pW[((size_t)(nblk0 + j) * KBW + kb) * 32 + lane];
            #pragma unroll
            for (int i = 0; i < 2; i++) {
                mma16(acc[0][i][j], (const uint32_t*)&ah[i], b.x, b.y);
                mma16(acc[0][i][j], (const uint32_t*)&ah[i], b.z, b.w);
                mma16(acc[0][i][j], (const uint32_t*)&al[i], b.x, b.y);
            }
        }
    }
    // ---- aggs region: 3 weight streams ----
    #pragma unroll 1
    for (int kb = 0; kb < KBA; kb++) {
        uint4 ah[2], al[2];
        #pragma unroll
        for (int i = 0; i < 2; i++) {
            size_t ai = (((size_t)(mblk0 + i) * KBA + kb) * 32 + lane) * 2;
            ah[i] = pA[ai]; al[i] = pA[ai + 1];
        }
        #pragma unroll
        for (int s = 0; s < 3; s++) {
            const int kbg = KBX + s * KBA + kb;
            #pragma unroll
            for (int j = 0; j < 4; j++) {
                uint4 b = pW[((size_t)(nblk0 + j) * KBW + kbg) * 32 + lane];
                #pragma unroll
                for (int i = 0; i < 2; i++) {
                    mma16(acc[s][i][j], (const uint32_t*)&ah[i], b.x, b.y);
                    mma16(acc[s][i][j], (const uint32_t*)&ah[i], b.z, b.w);
                    mma16(acc[s][i][j], (const uint32_t*)&al[i], b.x, b.y);
                }
            }
        }
    }
    __syncthreads();

    // ---- epilogue ----
    const int m0w = blockIdx.x * 64 + warpM * 32;
    const int n0w = blockIdx.y * 64 + warpN * 32;
    float ampv[2][2], attv[2][2];
    #pragma unroll
    for (int i = 0; i < 2; i++) {
        int ra = m0w + i * 16 + gr, rb = ra + 8;
        int rac = ra < NN ? ra : NN - 1, rbc = rb < NN ? rb : NN - 1;
        ampv[i][0] = g_amp[rac]; ampv[i][1] = g_amp[rbc];
        attv[i][0] = g_att[rac]; attv[i][1] = g_att[rbc];
    }
    #pragma unroll
    for (int j = 0; j < 4; j++) {
        const int col = n0w + j * 8 + tig * 2;
        const float bs0 = bias[col], bs1 = bias[col + 1];
        float cs0 = 0.f, css0 = 0.f, cs1 = 0.f, css1 = 0.f;
        #pragma unroll
        for (int i = 0; i < 2; i++) {
            int ra = m0w + i * 16 + gr, rb = ra + 8;
            float v00 = fmaxf(acc[0][i][j][0] + ampv[i][0] * acc[1][i][j][0] +
                              attv[i][0] * acc[2][i][j][0] + bs0, 0.f);
            float v01 = fmaxf(acc[0][i][j][1] + ampv[i][0] * acc[1][i][j][1] +
                              attv[i][0] * acc[2][i][j][1] + bs1, 0.f);
            float v10 = fmaxf(acc[0][i][j][2] + ampv[i][1] * acc[1][i][j][2] +
                              attv[i][1] * acc[2][i][j][2] + bs0, 0.f);
            float v11 = fmaxf(acc[0][i][j][3] + ampv[i][1] * acc[1][i][j][3] +
                              attv[i][1] * acc[2][i][j][3] + bs1, 0.f);
            if (ra < NN) {
                *(float2*)(out + (size_t)ra * DOUT + col) = make_float2(v00, v01);
                cs0 += v00; css0 = fmaf(v00, v00, css0);
                cs1 += v01; css1 = fmaf(v01, v01, css1);
            }
            if (rb < NN) {
                *(float2*)(out + (size_t)rb * DOUT + col) = make_float2(v10, v11);
                cs0 += v10; css0 = fmaf(v10, v10, css0);
                cs1 += v11; css1 = fmaf(v11, v11, css1);
            }
        }
        #pragma unroll
        for (int off = 16; off >= 4; off >>= 1) {
            cs0 += __shfl_xor_sync(0xffffffffu, cs0, off);
            css0 += __shfl_xor_sync(0xffffffffu, css0, off);
            cs1 += __shfl_xor_sync(0xffffffffu, cs1, off);
            css1 += __shfl_xor_sync(0xffffffffu, css1, off);
        }
        if (gr == 0) {
            int lc = warpN * 32 + j * 8 + tig * 2;
            atomicAdd(&scs[lc], cs0);
            atomicAdd(&scss[lc], css0);
            atomicAdd(&scs[lc + 1], cs1);
            atomicAdd(&scss[lc + 1], css1);
        }
    }
    __syncthreads();
    if (tid < 64) {
        atomicAdd(&g_colsum[blockIdx.y * 64 + tid], scs[tid]);
        atomicAdd(&g_colsumsq[blockIdx.y * 64 + tid], scss[tid]);
    }
}

// stats + re-zero accumulators for the next layer (single block!)
__global__ void k_stats(const float* __restrict__ gamma,
                        const float* __restrict__ beta, int dout) {
    int c = threadIdx.x;
    if (c < dout) {
        float mean = g_colsum[c] / (float)NN;
        float var = fmaxf(g_colsumsq[c] / (float)NN - mean * mean, 0.f);
        float sc = gamma[c] * rsqrtf(var + EPSW);
        g_s[c] = sc;
        g_t[c] = beta[c] - mean * sc;
    }
    __syncthreads();
    if (c < 256) { g_colsum[c] = 0.f; g_colsumsq[c] = 0.f; }
}

// ---------- classifier ----------
__global__ void k_foldcls(const float* __restrict__ Wc, const float* __restrict__ bc) {
    int tid = threadIdx.x;
    if (tid < 640) {
        int c = tid / 10;
        g_wc2[tid] = g_s[c] * Wc[tid];
    }
    if (tid < 10) {
        float acc = bc[tid];
        for (int c = 0; c < 64; c++) acc = fmaf(g_t[c], Wc[c * 10 + tid], acc);
        g_bc2[tid] = acc;
    }
}
__global__ void k_cls(const float* __restrict__ r, float* __restrict__ out) {
    __shared__ float w[640];
    __shared__ float b[10];
    int tid = threadIdx.x;
    for (int i = tid; i < 640; i += blockDim.x) w[i] = g_wc2[i];
    if (tid < 10) b[tid] = g_bc2[tid];
    __syncthreads();
    int warp = (blockIdx.x * blockDim.x + tid) >> 5;
    int lane = tid & 31;
    if (warp >= NN) return;
    float v0 = r[(size_t)warp * 64 + lane];
    float v1 = r[(size_t)warp * 64 + 32 + lane];
    float acc[10];
    #pragma unroll
    for (int j = 0; j < 10; j++)
        acc[j] = v0 * w[lane * 10 + j] + v1 * w[(32 + lane) * 10 + j];
    #pragma unroll
    for (int off = 16; off; off >>= 1)
        #pragma unroll
        for (int j = 0; j < 10; j++)
            acc[j] += __shfl_xor_sync(0xffffffffu, acc[j], off);
    if (lane < 10) out[(size_t)warp * 10 + lane] = acc[lane] + b[lane];
}

// ---------- launch ----------
extern "C" void kernel_launch(void* const* d_in, const int* in_sizes, int n_in,
                              void* d_out, int out_size) {
    const float* x  = (const float*)d_in[0];
    const int*   ei = (const int*)d_in[1];
    const float* W1 = (const float*)d_in[2];
    const float* b1 = (const float*)d_in[3];
    const float* ga1 = (const float*)d_in[4];
    const float* be1 = (const float*)d_in[5];
    const float* W2 = (const float*)d_in[6];
    const float* b2 = (const float*)d_in[7];
    const float* ga2 = (const float*)d_in[8];
    const float* be2 = (const float*)d_in[9];
    const float* W3 = (const float*)d_in[10];
    const float* b3 = (const float*)d_in[11];
    const float* ga3 = (const float*)d_in[12];
    const float* be3 = (const float*)d_in[13];
    const float* W4 = (const float*)d_in[14];
    const float* b4 = (const float*)d_in[15];
    const float* ga4 = (const float*)d_in[16];
    const float* be4 = (const float*)d_in[17];
    const float* Wc = (const float*)d_in[18];
    const float* bc = (const float*)d_in[19];
    float* out = (float*)d_out;

    float *p_h0, *p_h1;
    uint4 *pX, *pA, *pw1, *pw2, *pw3, *pw4;
    cudaGetSymbolAddress((void**)&p_h0, g_h0);
    cudaGetSymbolAddress((void**)&p_h1, g_h1);
    cudaGetSymbolAddress((void**)&pX, g_packX);
    cudaGetSymbolAddress((void**)&pA, g_packAgg);
    cudaGetSymbolAddress((void**)&pw1, g_wp1);
    cudaGetSymbolAddress((void**)&pw2, g_wp2);
    cudaGetSymbolAddress((void**)&pw3, g_wp3);
    cudaGetSymbolAddress((void**)&pw4, g_wp4);

    // preprocessing: slots 0-4; slot 5 = k_aggp<64> (ncu window target)
    k_init<<<(NN + 255) / 256, 256>>>();
    k_degcnt<<<EE / 256, 256>>>(ei);
    k_logdeg<<<(NN + 255) / 256, 256>>>();
    k_scan2<<<SCAN_BLOCKS, 1024>>>();
    k_scatter<<<EE / 256, 256>>>(ei);

    // ---- layer 1: 64 -> 128 ----
    k_aggp<64><<<dim3(NBLK16, 2), 256>>>(x, pA);
    k_packW<<<(16 * 52 * 32 + 255) / 256, 256>>>(W1, pw1, 832, 128);
    k_packW<<<(32 * 104 * 32 + 255) / 256, 256>>>(W2, pw2, 1664, 256);
    k_packW<<<(16 * 208 * 32 + 255) / 256, 256>>>(W3, pw3, 3328, 128);
    k_packW<<<(8 * 104 * 32 + 255) / 256, 256>>>(W4, pw4, 1664, 64);
    k_packA<<<dim3(NBLK16, 1), 128>>>(x, pX, 64);
    k_gemm_bf<64, 128><<<dim3(NPAD / 64, 2), 128>>>(pX, pA, pw1, b1, p_h0);
    k_stats<<<1, 256>>>(ga1, be1, 128);

    // ---- layer 2: 128 -> 256 ----
    k_aggp<128><<<dim3(NBLK16, 4), 256>>>(p_h0, pA);
    k_packA<<<dim3(NBLK16, 2), 128>>>(p_h0, pX, 128);
    k_gemm_bf<128, 256><<<dim3(NPAD / 64, 4), 128>>>(pX, pA, pw2, b2, p_h1);
    k_stats<<<1, 256>>>(ga2, be2, 256);

    // ---- layer 3: 256 -> 128 ----
    k_aggp<256><<<dim3(NBLK16, 8), 256>>>(p_h1, pA);
    k_packA<<<dim3(NBLK16, 4), 128>>>(p_h1, pX, 256);
    k_gemm_bf<256, 128><<<dim3(NPAD / 64, 2), 128>>>(pX, pA, pw3, b3, p_h0);
    k_stats<<<1, 256>>>(ga3, be3, 128);

    // ---- layer 4: 128 -> 64 ----
    k_aggp<128><<<dim3(NBLK16, 4), 256>>>(p_h0, pA);
    k_packA<<<dim3(NBLK16, 2), 128>>>(p_h0, pX, 128);
    k_gemm_bf<128, 64><<<dim3(NPAD / 64, 1), 128>>>(pX, pA, pw4, b4, p_h1);
    k_stats<<<1, 256>>>(ga4, be4, 64);

    // ---- classifier ----
    k_foldcls<<<1, 640>>>(Wc, bc);
    k_cls<<<((size_t)NN * 32 + 255) / 256, 256>>>(p_h1, out);
}

// round 9
// speedup vs baseline: 1.8477x; 1.0475x over previous
#include <cuda_runtime.h>
#include <cuda_bf16.h>
#include <math.h>
#include <stdint.h>

#define NN 50000
#define EE 800000
#define EPSW 1e-5f
#define NPAD 50048          // 391 * 128
#define NBLK16 3128         // NPAD / 16
#define SCAN_BLOCKS 49      // ceil(NN / 1024)

// ---------- helpers ----------
__device__ __forceinline__ uint32_t pk2(float e0, float e1) {
    uint32_t r;
    asm("cvt.rn.bf16x2.f32 %0, %1, %2;" : "=r"(r) : "f"(e1), "f"(e0));
    return r;
}
__device__ __forceinline__ float bfrt(float x) {
    return __bfloat162float(__float2bfloat16(x));
}
__device__ __forceinline__ void mma16(float* c, const uint32_t* a,
                                      uint32_t b0, uint32_t b1) {
    asm volatile("mma.sync.aligned.m16n8k16.row.col.f32.bf16.bf16.f32 "
                 "{%0,%1,%2,%3}, {%4,%5,%6,%7}, {%8,%9}, {%0,%1,%2,%3};"
                 : "+f"(c[0]), "+f"(c[1]), "+f"(c[2]), "+f"(c[3])
                 : "r"(a[0]), "r"(a[1]), "r"(a[2]), "r"(a[3]), "r"(b0), "r"(b1));
}

// ---------- scratch ----------
__device__ float g_deg[NN];
__device__ float g_logdeg[NN];
__device__ float g_amp[NN];
__device__ float g_att[NN];
__device__ float g_logsum;
__device__ int   g_rowptr[NN + 1];
__device__ int   g_cursor[NN];
__device__ int   g_col[EE];
__device__ float g_h0[(size_t)NN * 256];
__device__ float g_h1[(size_t)NN * 256];
__device__ float g_colsum[256];
__device__ float g_colsumsq[256];
__device__ float g_s[256];
__device__ float g_t[256];
__device__ float g_wc2[64 * 10];
__device__ float g_bc2[10];
__device__ int   g_bsum[64];
__device__ int   g_bpre[64];
__device__ int   g_bflag[64];
__device__ uint4 g_packX[(size_t)NBLK16 * 16 * 32 * 2];
__device__ uint4 g_packAgg[(size_t)NBLK16 * 64 * 32 * 2];
__device__ uint4 g_wp1[16 * 52 * 32];
__device__ uint4 g_wp2[32 * 104 * 32];
__device__ uint4 g_wp3[16 * 208 * 32];
__device__ uint4 g_wp4[8 * 104 * 32];

// ---------- preprocessing ----------
__global__ void k_init() {
    int i = blockIdx.x * blockDim.x + threadIdx.x;
    if (i < NN) g_deg[i] = 0.f;
    if (i < 256) { g_s[i] = 1.f; g_t[i] = 0.f; g_colsum[i] = 0.f; g_colsumsq[i] = 0.f; }
    if (i < 64) g_bflag[i] = 0;
    if (i == 0) g_logsum = 0.f;
}
__global__ void k_degcnt(const int* __restrict__ ei) {
    int e = blockIdx.x * blockDim.x + threadIdx.x;
    if (e < EE) atomicAdd(&g_deg[ei[EE + e]], 1.f);
}
__global__ void k_logdeg() {
    int n = blockIdx.x * blockDim.x + threadIdx.x;
    float ld = 0.f;
    if (n < NN) { ld = log1pf(g_deg[n]); g_logdeg[n] = ld; }
    __shared__ float sh[256];
    sh[threadIdx.x] = ld;
    __syncthreads();
    for (int off = 128; off; off >>= 1) {
        if (threadIdx.x < off) sh[threadIdx.x] += sh[threadIdx.x + off];
        __syncthreads();
    }
    if (threadIdx.x == 0) atomicAdd(&g_logsum, sh[0]);
}
__global__ void k_scan2() {
    __shared__ int wsum[32];
    __shared__ int s_off;
    const int tid = threadIdx.x, lane = tid & 31, wid = tid >> 5;
    const int bid = blockIdx.x;
    const int i = bid * 1024 + tid;
    const float delta = g_logsum / (float)NN;
    int v = 0;
    if (i < NN) {
        v = (int)g_deg[i];
        float ld = g_logdeg[i];
        g_amp[i] = ld / delta;
        g_att[i] = (ld > 0.f) ? delta / fmaxf(ld, 1e-6f) : 1.f;
    }
    int x = v;
    #pragma unroll
    for (int off = 1; off < 32; off <<= 1) {
        int y = __shfl_up_sync(0xffffffffu, x, off);
        if (lane >= off) x += y;
    }
    if (lane == 31) wsum[wid] = x;
    __syncthreads();
    if (wid == 0) {
        int w = wsum[lane];
        #pragma unroll
        for (int off = 1; off < 32; off <<= 1) {
            int y = __shfl_up_sync(0xffffffffu, w, off);
            if (lane >= off) w += y;
        }
        wsum[lane] = w;
    }
    __syncthreads();
    const int incl = x + (wid > 0 ? wsum[wid - 1] : 0);
    if (tid == 1023) {
        g_bsum[bid] = incl;
        __threadfence();
        if (bid == 0) {
            g_bpre[0] = incl;
            __threadfence();
            atomicExch(&g_bflag[0], 2);
        } else {
            atomicExch(&g_bflag[bid], 1);
        }
    }
    if (tid == 0) {
        int off = 0;
        if (bid > 0) {
            int p = bid - 1;
            while (p >= 0) {
                int f;
                do { f = atomicAdd(&g_bflag[p], 0); } while (f == 0);
                if (f == 2) { off += atomicAdd(&g_bpre[p], 0); break; }
                off += atomicAdd(&g_bsum[p], 0);
                p--;
            }
        }
        s_off = off;
    }
    __syncthreads();
    const int off = s_off;
    if (i < NN) {
        int ex = off + incl - v;
        g_rowptr[i] = ex;
        g_cursor[i] = ex;
        if (i == NN - 1) g_rowptr[NN] = off + incl;
    }
    if (tid == 1023 && bid > 0) {
        g_bpre[bid] = off + incl;
        __threadfence();
        atomicExch(&g_bflag[bid], 2);
    }
}
__global__ void k_scatter(const int* __restrict__ ei) {
    int e = blockIdx.x * blockDim.x + threadIdx.x;
    if (e >= EE) return;
    int dst = ei[EE + e];
    int pos = atomicAdd(&g_cursor[dst], 1);
    g_col[pos] = ei[e];
}

// ---------- weight pack ----------
__global__ void k_packW(const float* __restrict__ W, uint4* __restrict__ dst,
                        int K13, int DOUT) {
    int KBW = K13 / 16;
    int total = (DOUT / 8) * KBW * 32;
    int t = blockIdx.x * blockDim.x + threadIdx.x;
    if (t >= total) return;
    int lane = t & 31;
    int kb = (t >> 5) % KBW;
    int nblk = (t >> 5) / KBW;
    int gr = lane >> 2, tig = lane & 3;
    int n = nblk * 8 + gr;
    int k0 = kb * 16 + tig * 2;
    float w00 = W[(size_t)k0 * DOUT + n];
    float w01 = W[(size_t)(k0 + 1) * DOUT + n];
    float w80 = W[(size_t)(k0 + 8) * DOUT + n];
    float w81 = W[(size_t)(k0 + 9) * DOUT + n];
    uint4 o;
    o.x = pk2(w00, w01);
    o.y = pk2(w80, w81);
    o.z = pk2(w00 - bfrt(w00), w01 - bfrt(w01));
    o.w = pk2(w80 - bfrt(w80), w81 - bfrt(w81));
    dst[t] = o;
}

// ---------- X activation pack (BN affine) ----------
__global__ void k_packA(const float* __restrict__ src, uint4* __restrict__ dst,
                        int D) {
    __shared__ float sm[16][64];
    int tid = threadIdx.x;
    int gy = blockIdx.y * 64;
    #pragma unroll
    for (int tt = tid; tt < 256; tt += 128) {
        int row = tt >> 4, c4 = (tt & 15) * 4;
        int m = blockIdx.x * 16 + row;
        if (m >= NN) m = NN - 1;
        *(float4*)&sm[row][c4] = *(const float4*)(src + (size_t)m * D + gy + c4);
    }
    __syncthreads();
    int kb = tid >> 5, lane = tid & 31;
    int gr = lane >> 2, tig = lane & 3;
    int c0 = kb * 16 + tig * 2;
    float v[8];
    #pragma unroll
    for (int h = 0; h < 2; h++) {
        int c = c0 + h * 8;
        float s0 = g_s[gy + c], t0 = g_t[gy + c];
        float s1 = g_s[gy + c + 1], t1 = g_t[gy + c + 1];
        v[h * 4 + 0] = fmaf(s0, sm[gr][c], t0);
        v[h * 4 + 1] = fmaf(s1, sm[gr][c + 1], t1);
        v[h * 4 + 2] = fmaf(s0, sm[gr + 8][c], t0);
        v[h * 4 + 3] = fmaf(s1, sm[gr + 8][c + 1], t1);
    }
    uint4 hi, lo;
    hi.x = pk2(v[0], v[1]);
    hi.y = pk2(v[2], v[3]);
    hi.z = pk2(v[4], v[5]);
    hi.w = pk2(v[6], v[7]);
    lo.x = pk2(v[0] - bfrt(v[0]), v[1] - bfrt(v[1]));
    lo.y = pk2(v[2] - bfrt(v[2]), v[3] - bfrt(v[3]));
    lo.z = pk2(v[4] - bfrt(v[4]), v[5] - bfrt(v[5]));
    lo.w = pk2(v[6] - bfrt(v[6]), v[7] - bfrt(v[7]));
    int KB = D / 16;
    size_t idx = (((size_t)blockIdx.x * KB + (blockIdx.y * 4 + kb)) * 32 + lane) * 2;
    dst[idx] = hi;
    dst[idx + 1] = lo;
}

// ---------- fused aggregation + fragment pack (MLP-4 edge loop) ----------
template <int DIN>
__global__ void __launch_bounds__(256) k_aggp(const float* __restrict__ in,
                                              uint4* __restrict__ pA) {
    constexpr int KBA = DIN / 4;
    __shared__ float sm[16][4][33];
    const int tid = threadIdx.x, lane = tid & 31, w = tid >> 5;
    const int nb = blockIdx.x * 16;
    const int c = blockIdx.y * 32 + lane;
    const float s = g_s[c], t = g_t[c];
    #pragma unroll
    for (int u = 0; u < 2; u++) {
        int nloc = w * 2 + u;
        int n = nb + nloc; if (n >= NN) n = NN - 1;
        int beg = g_rowptr[n], end = g_rowptr[n + 1];
        float sum = 0.f, ss = 0.f, mn = INFINITY, mx = -INFINITY;
        int j = beg;
        for (; j + 3 < end; j += 4) {
            int s0 = g_col[j], s1 = g_col[j + 1], s2 = g_col[j + 2], s3 = g_col[j + 3];
            float v0 = in[(size_t)s0 * DIN + c];
            float v1 = in[(size_t)s1 * DIN + c];
            float v2 = in[(size_t)s2 * DIN + c];
            float v3 = in[(size_t)s3 * DIN + c];
            v0 = fmaf(s, v0, t); v1 = fmaf(s, v1, t);
            v2 = fmaf(s, v2, t); v3 = fmaf(s, v3, t);
            sum += v0 + v1 + v2 + v3;
            ss = fmaf(v0, v0, ss); ss = fmaf(v1, v1, ss);
            ss = fmaf(v2, v2, ss); ss = fmaf(v3, v3, ss);
            mn = fminf(mn, fminf(fminf(v0, v1), fminf(v2, v3)));
            mx = fmaxf(mx, fmaxf(fmaxf(v0, v1), fmaxf(v2, v3)));
        }
        for (; j < end; j++) {
            float v = fmaf(s, in[(size_t)g_col[j] * DIN + c], t);
            sum += v; ss = fmaf(v, v, ss);
            mn = fminf(mn, v); mx = fmaxf(mx, v);
        }
        float deg = (float)(end - beg);
        float cnt = fmaxf(deg, 1.f);
        float mean = sum / cnt;
        float var = fmaxf(ss / cnt - mean * mean, 0.f);
        float sd = sqrtf(var + EPSW);
        bool has = end > beg;
        sm[nloc][0][lane] = mean;
        sm[nloc][1][lane] = has ? mn : 0.f;
        sm[nloc][2][lane] = has ? mx : 0.f;
        sm[nloc][3][lane] = sd;
    }
    __syncthreads();
    const int a = w >> 1, h = w & 1;
    const int gr = lane >> 2, tig = lane & 3;
    const int t2 = h * 16 + tig * 2;
    float v0 = sm[gr][a][t2],         v1 = sm[gr][a][t2 + 1];
    float v2 = sm[gr + 8][a][t2],     v3 = sm[gr + 8][a][t2 + 1];
    float v4 = sm[gr][a][t2 + 8],     v5 = sm[gr][a][t2 + 9];
    float v6 = sm[gr + 8][a][t2 + 8], v7 = sm[gr + 8][a][t2 + 9];
    uint4 hi, lo;
    hi.x = pk2(v0, v1); hi.y = pk2(v2, v3);
    hi.z = pk2(v4, v5); hi.w = pk2(v6, v7);
    lo.x = pk2(v0 - bfrt(v0), v1 - bfrt(v1));
    lo.y = pk2(v2 - bfrt(v2), v3 - bfrt(v3));
    lo.z = pk2(v4 - bfrt(v4), v5 - bfrt(v5));
    lo.w = pk2(v6 - bfrt(v6), v7 - bfrt(v7));
    const int kb = a * (DIN / 16) + blockIdx.y * 2 + h;
    size_t idx = (((size_t)blockIdx.x * KBA + kb) * 32 + lane) * 2;
    pA[idx] = hi;
    pA[idx + 1] = lo;
}

// ---------- bf16x2 3-pass fused PNA GEMM ----------
// CTA 128M x 32N, 4 warps (2M x 2N), warp tile 64M x 16N via m16n8k16.
// B-load reuse: each B uint4 feeds 12 MMAs (4 i-blocks x 3 passes).
template <int DIN, int DOUT>
__global__ void __launch_bounds__(128) k_gemm_bf(const uint4* __restrict__ pX,
                                                 const uint4* __restrict__ pA,
                                                 const uint4* __restrict__ pW,
                                                 const float* __restrict__ bias,
                                                 float* __restrict__ out) {
    constexpr int KBX = DIN / 16;
    constexpr int KBA = DIN / 4;
    constexpr int KBW = 13 * DIN / 16;
    __shared__ float scs[32], scss[32];
    const int tid = threadIdx.x, lane = tid & 31, wid = tid >> 5;
    const int warpM = wid & 1, warpN = wid >> 1;
    const int gr = lane >> 2, tig = lane & 3;
    const int mblk0 = blockIdx.x * 8 + warpM * 4;
    const int nblk0 = blockIdx.y * 4 + warpN * 2;

    if (tid < 32) { scs[tid] = 0.f; scss[tid] = 0.f; }

    float acc[3][4][2][4];
    #pragma unroll
    for (int s = 0; s < 3; s++)
        #pragma unroll
        for (int i = 0; i < 4; i++)
            #pragma unroll
            for (int j = 0; j < 2; j++)
                #pragma unroll
                for (int q = 0; q < 4; q++) acc[s][i][j][q] = 0.f;

    // ---- x region ----
    #pragma unroll 1
    for (int kb = 0; kb < KBX; kb++) {
        uint4 ah[4], al[4];
        #pragma unroll
        for (int i = 0; i < 4; i++) {
            size_t ai = (((size_t)(mblk0 + i) * KBX + kb) * 32 + lane) * 2;
            ah[i] = pX[ai]; al[i] = pX[ai + 1];
        }
        #pragma unroll
        for (int j = 0; j < 2; j++) {
            uint4 b = pW[((size_t)(nblk0 + j) * KBW + kb) * 32 + lane];
            #pragma unroll
            for (int i = 0; i < 4; i++) {
                mma16(acc[0][i][j], (const uint32_t*)&ah[i], b.x, b.y);
                mma16(acc[0][i][j], (const uint32_t*)&ah[i], b.z, b.w);
                mma16(acc[0][i][j], (const uint32_t*)&al[i], b.x, b.y);
            }
        }
    }
    // ---- aggs region: 3 weight streams ----
    #pragma unroll 1
    for (int kb = 0; kb < KBA; kb++) {
        uint4 ah[4], al[4];
        #pragma unroll
        for (int i = 0; i < 4; i++) {
            size_t ai = (((size_t)(mblk0 + i) * KBA + kb) * 32 + lane) * 2;
            ah[i] = pA[ai]; al[i] = pA[ai + 1];
        }
        #pragma unroll
        for (int s = 0; s < 3; s++) {
            const int kbg = KBX + s * KBA + kb;
            #pragma unroll
            for (int j = 0; j < 2; j++) {
                uint4 b = pW[((size_t)(nblk0 + j) * KBW + kbg) * 32 + lane];
                #pragma unroll
                for (int i = 0; i < 4; i++) {
                    mma16(acc[s][i][j], (const uint32_t*)&ah[i], b.x, b.y);
                    mma16(acc[s][i][j], (const uint32_t*)&ah[i], b.z, b.w);
                    mma16(acc[s][i][j], (const uint32_t*)&al[i], b.x, b.y);
                }
            }
        }
    }
    __syncthreads();

    // ---- epilogue ----
    const int m0w = blockIdx.x * 128 + warpM * 64;
    const int n0w = blockIdx.y * 32 + warpN * 16;
    float ampv[4][2], attv[4][2];
    #pragma unroll
    for (int i = 0; i < 4; i++) {
        int ra = m0w + i * 16 + gr, rb = ra + 8;
        int rac = ra < NN ? ra : NN - 1, rbc = rb < NN ? rb : NN - 1;
        ampv[i][0] = g_amp[rac]; ampv[i][1] = g_amp[rbc];
        attv[i][0] = g_att[rac]; attv[i][1] = g_att[rbc];
    }
    #pragma unroll
    for (int j = 0; j < 2; j++) {
        const int col = n0w + j * 8 + tig * 2;
        const float bs0 = bias[col], bs1 = bias[col + 1];
        float cs0 = 0.f, css0 = 0.f, cs1 = 0.f, css1 = 0.f;
        #pragma unroll
        for (int i = 0; i < 4; i++) {
            int ra = m0w + i * 16 + gr, rb = ra + 8;
            float v00 = fmaxf(acc[0][i][j][0] + ampv[i][0] * acc[1][i][j][0] +
                              attv[i][0] * acc[2][i][j][0] + bs0, 0.f);
            float v01 = fmaxf(acc[0][i][j][1] + ampv[i][0] * acc[1][i][j][1] +
                              attv[i][0] * acc[2][i][j][1] + bs1, 0.f);
            float v10 = fmaxf(acc[0][i][j][2] + ampv[i][1] * acc[1][i][j][2] +
                              attv[i][1] * acc[2][i][j][2] + bs0, 0.f);
            float v11 = fmaxf(acc[0][i][j][3] + ampv[i][1] * acc[1][i][j][3] +
                              attv[i][1] * acc[2][i][j][3] + bs1, 0.f);
            if (ra < NN) {
                *(float2*)(out + (size_t)ra * DOUT + col) = make_float2(v00, v01);
                cs0 += v00; css0 = fmaf(v00, v00, css0);
                cs1 += v01; css1 = fmaf(v01, v01, css1);
            }
            if (rb < NN) {
                *(float2*)(out + (size_t)rb * DOUT + col) = make_float2(v10, v11);
                cs0 += v10; css0 = fmaf(v10, v10, css0);
                cs1 += v11; css1 = fmaf(v11, v11, css1);
            }
        }
        #pragma unroll
        for (int off = 16; off >= 4; off >>= 1) {
            cs0 += __shfl_xor_sync(0xffffffffu, cs0, off);
            css0 += __shfl_xor_sync(0xffffffffu, css0, off);
            cs1 += __shfl_xor_sync(0xffffffffu, cs1, off);
            css1 += __shfl_xor_sync(0xffffffffu, css1, off);
        }
        if (gr == 0) {
            int lc = warpN * 16 + j * 8 + tig * 2;
            atomicAdd(&scs[lc], cs0);
            atomicAdd(&scss[lc], css0);
            atomicAdd(&scs[lc + 1], cs1);
            atomicAdd(&scss[lc + 1], css1);
        }
    }
    __syncthreads();
    if (tid < 32) {
        atomicAdd(&g_colsum[blockIdx.y * 32 + tid], scs[tid]);
        atomicAdd(&g_colsumsq[blockIdx.y * 32 + tid], scss[tid]);
    }
}

// stats + re-zero accumulators (single block)
__global__ void k_stats(const float* __restrict__ gamma,
                        const float* __restrict__ beta, int dout) {
    int c = threadIdx.x;
    if (c < dout) {
        float mean = g_colsum[c] / (float)NN;
        float var = fmaxf(g_colsumsq[c] / (float)NN - mean * mean, 0.f);
        float sc = gamma[c] * rsqrtf(var + EPSW);
        g_s[c] = sc;
        g_t[c] = beta[c] - mean * sc;
    }
    __syncthreads();
    if (c < 256) { g_colsum[c] = 0.f; g_colsumsq[c] = 0.f; }
}

// ---------- classifier ----------
__global__ void k_foldcls(const float* __restrict__ Wc, const float* __restrict__ bc) {
    int tid = threadIdx.x;
    if (tid < 640) {
        int c = tid / 10;
        g_wc2[tid] = g_s[c] * Wc[tid];
    }
    if (tid < 10) {
        float acc = bc[tid];
        for (int c = 0; c < 64; c++) acc = fmaf(g_t[c], Wc[c * 10 + tid], acc);
        g_bc2[tid] = acc;
    }
}
__global__ void k_cls(const float* __restrict__ r, float* __restrict__ out) {
    __shared__ float w[640];
    __shared__ float b[10];
    int tid = threadIdx.x;
    for (int i = tid; i < 640; i += blockDim.x) w[i] = g_wc2[i];
    if (tid < 10) b[tid] = g_bc2[tid];
    __syncthreads();
    int warp = (blockIdx.x * blockDim.x + tid) >> 5;
    int lane = tid & 31;
    if (warp >= NN) return;
    float v0 = r[(size_t)warp * 64 + lane];
    float v1 = r[(size_t)warp * 64 + 32 + lane];
    float acc[10];
    #pragma unroll
    for (int j = 0; j < 10; j++)
        acc[j] = v0 * w[lane * 10 + j] + v1 * w[(32 + lane) * 10 + j];
    #pragma unroll
    for (int off = 16; off; off >>= 1)
        #pragma unroll
        for (int j = 0; j < 10; j++)
            acc[j] += __shfl_xor_sync(0xffffffffu, acc[j], off);
    if (lane < 10) out[(size_t)warp * 10 + lane] = acc[lane] + b[lane];
}

// ---------- launch ----------
extern "C" void kernel_launch(void* const* d_in, const int* in_sizes, int n_in,
                              void* d_out, int out_size) {
    const float* x  = (const float*)d_in[0];
    const int*   ei = (const int*)d_in[1];
    const float* W1 = (const float*)d_in[2];
    const float* b1 = (const float*)d_in[3];
    const float* ga1 = (const float*)d_in[4];
    const float* be1 = (const float*)d_in[5];
    const float* W2 = (const float*)d_in[6];
    const float* b2 = (const float*)d_in[7];
    const float* ga2 = (const float*)d_in[8];
    const float* be2 = (const float*)d_in[9];
    const float* W3 = (const float*)d_in[10];
    const float* b3 = (const float*)d_in[11];
    const float* ga3 = (const float*)d_in[12];
    const float* be3 = (const float*)d_in[13];
    const float* W4 = (const float*)d_in[14];
    const float* b4 = (const float*)d_in[15];
    const float* ga4 = (const float*)d_in[16];
    const float* be4 = (const float*)d_in[17];
    const float* Wc = (const float*)d_in[18];
    const float* bc = (const float*)d_in[19];
    float* out = (float*)d_out;

    float *p_h0, *p_h1;
    uint4 *pX, *pA, *pw1, *pw2, *pw3, *pw4;
    cudaGetSymbolAddress((void**)&p_h0, g_h0);
    cudaGetSymbolAddress((void**)&p_h1, g_h1);
    cudaGetSymbolAddress((void**)&pX, g_packX);
    cudaGetSymbolAddress((void**)&pA, g_packAgg);
    cudaGetSymbolAddress((void**)&pw1, g_wp1);
    cudaGetSymbolAddress((void**)&pw2, g_wp2);
    cudaGetSymbolAddress((void**)&pw3, g_wp3);
    cudaGetSymbolAddress((void**)&pw4, g_wp4);

    // preprocessing
    k_init<<<(NN + 255) / 256, 256>>>();
    k_degcnt<<<EE / 256, 256>>>(ei);
    k_logdeg<<<(NN + 255) / 256, 256>>>();
    k_scan2<<<SCAN_BLOCKS, 1024>>>();
    k_scatter<<<EE / 256, 256>>>(ei);

    // ---- layer 1: 64 -> 128 ----
    k_aggp<64><<<dim3(NBLK16, 2), 256>>>(x, pA);
    k_packW<<<(16 * 52 * 32 + 255) / 256, 256>>>(W1, pw1, 832, 128);
    k_packW<<<(32 * 104 * 32 + 255) / 256, 256>>>(W2, pw2, 1664, 256);
    k_packW<<<(16 * 208 * 32 + 255) / 256, 256>>>(W3, pw3, 3328, 128);
    k_packW<<<(8 * 104 * 32 + 255) / 256, 256>>>(W4, pw4, 1664, 64);
    k_packA<<<dim3(NBLK16, 1), 128>>>(x, pX, 64);
    k_gemm_bf<64, 128><<<dim3(NPAD / 128, 4), 128>>>(pX, pA, pw1, b1, p_h0);
    k_stats<<<1, 256>>>(ga1, be1, 128);

    // ---- layer 2: 128 -> 256 ----
    k_aggp<128><<<dim3(NBLK16, 4), 256>>>(p_h0, pA);
    k_packA<<<dim3(NBLK16, 2), 128>>>(p_h0, pX, 128);
    k_gemm_bf<128, 256><<<dim3(NPAD / 128, 8), 128>>>(pX, pA, pw2, b2, p_h1);
    k_stats<<<1, 256>>>(ga2, be2, 256);

    // ---- layer 3: 256 -> 128 ----
    k_aggp<256><<<dim3(NBLK16, 8), 256>>>(p_h1, pA);
    k_packA<<<dim3(NBLK16, 4), 128>>>(p_h1, pX, 256);
    k_gemm_bf<256, 128><<<dim3(NPAD / 128, 4), 128>>>(pX, pA, pw3, b3, p_h0);
    k_stats<<<1, 256>>>(ga3, be3, 128);

    // ---- layer 4: 128 -> 64 ----
    k_aggp<128><<<dim3(NBLK16, 4), 256>>>(p_h0, pA);
    k_packA<<<dim3(NBLK16, 2), 128>>>(p_h0, pX, 128);
    k_gemm_bf<128, 64><<<dim3(NPAD / 128, 2), 128>>>(pX, pA, pw4, b4, p_h1);
    k_stats<<<1, 256>>>(ga4, be4, 64);

    // ---- classifier ----
    k_foldcls<<<1, 640>>>(Wc, bc);
    k_cls<<<((size_t)NN * 32 + 255) / 256, 256>>>(p_h1, out);
}

// round 13
// speedup vs baseline: 2.4311x; 1.3157x over previous
#include <cuda_runtime.h>
#include <cuda_bf16.h>
#include <math.h>
#include <stdint.h>

#define NN 50000
#define EE 800000
#define EPSW 1e-5f
#define NPAD 50048          // 391 * 128
#define NBLK16 3128         // NPAD / 16
#define SCAN_BLOCKS 49

// ---------- helpers ----------
__device__ __forceinline__ uint32_t pk2(float e0, float e1) {
    uint32_t r;
    asm("cvt.rn.bf16x2.f32 %0, %1, %2;" : "=r"(r) : "f"(e1), "f"(e0));
    return r;
}
__device__ __forceinline__ float bfrt(float x) {
    return __bfloat162float(__float2bfloat16(x));
}
__device__ __forceinline__ void mma16(float* c, const uint32_t* a,
                                      uint32_t b0, uint32_t b1) {
    asm volatile("mma.sync.aligned.m16n8k16.row.col.f32.bf16.bf16.f32 "
                 "{%0,%1,%2,%3}, {%4,%5,%6,%7}, {%8,%9}, {%0,%1,%2,%3};"
                 : "+f"(c[0]), "+f"(c[1]), "+f"(c[2]), "+f"(c[3])
                 : "r"(a[0]), "r"(a[1]), "r"(a[2]), "r"(a[3]), "r"(b0), "r"(b1));
}

// ---------- scratch ----------
__device__ float g_deg[NN];
__device__ float g_logdeg[NN];
__device__ float g_amp[NN];
__device__ float g_att[NN];
__device__ float g_logsum;
__device__ int   g_rowptr[NN + 1];
__device__ int   g_cursor[NN];
__device__ int   g_col[EE];
__device__ float g_h0[(size_t)NN * 256];
__device__ float g_h1[(size_t)NN * 256];
__device__ float g_colsum[256];
__device__ float g_colsumsq[256];
__device__ float g_s[256];
__device__ float g_t[256];
__device__ float g_bias2[256];
__device__ float g_wc2[64 * 10];
__device__ float g_bc2[10];
__device__ int   g_bsum[64];
__device__ int   g_bpre[64];
__device__ int   g_bflag[64];
__device__ uint4 g_pX0[(size_t)NBLK16 * 16 * 32 * 2];
__device__ uint4 g_pX1[(size_t)NBLK16 * 16 * 32 * 2];
__device__ uint4 g_packAgg[(size_t)NBLK16 * 64 * 32 * 2];
__device__ uint4 g_wp1[16 * 52 * 32];
__device__ uint4 g_wp2[32 * 104 * 32];
__device__ uint4 g_wp3[16 * 208 * 32];
__device__ uint4 g_wp4[8 * 104 * 32];

// ---------- preprocessing ----------
__global__ void k_init() {
    int i = blockIdx.x * blockDim.x + threadIdx.x;
    if (i < NN) g_deg[i] = 0.f;
    if (i < 256) { g_s[i] = 1.f; g_t[i] = 0.f; g_colsum[i] = 0.f; g_colsumsq[i] = 0.f; }
    if (i < 64) g_bflag[i] = 0;
    if (i == 0) g_logsum = 0.f;
}
__global__ void k_degcnt(const int* __restrict__ ei) {
    int e = blockIdx.x * blockDim.x + threadIdx.x;
    if (e < EE) atomicAdd(&g_deg[ei[EE + e]], 1.f);
}
__global__ void k_logdeg() {
    int n = blockIdx.x * blockDim.x + threadIdx.x;
    float ld = 0.f;
    if (n < NN) { ld = log1pf(g_deg[n]); g_logdeg[n] = ld; }
    __shared__ float sh[256];
    sh[threadIdx.x] = ld;
    __syncthreads();
    for (int off = 128; off; off >>= 1) {
        if (threadIdx.x < off) sh[threadIdx.x] += sh[threadIdx.x + off];
        __syncthreads();
    }
    if (threadIdx.x == 0) atomicAdd(&g_logsum, sh[0]);
}
__global__ void k_scan2() {
    __shared__ int wsum[32];
    __shared__ int s_off;
    const int tid = threadIdx.x, lane = tid & 31, wid = tid >> 5;
    const int bid = blockIdx.x;
    const int i = bid * 1024 + tid;
    const float delta = g_logsum / (float)NN;
    int v = 0;
    if (i < NN) {
        v = (int)g_deg[i];
        float ld = g_logdeg[i];
        g_amp[i] = ld / delta;
        g_att[i] = (ld > 0.f) ? delta / fmaxf(ld, 1e-6f) : 1.f;
    }
    int x = v;
    #pragma unroll
    for (int off = 1; off < 32; off <<= 1) {
        int y = __shfl_up_sync(0xffffffffu, x, off);
        if (lane >= off) x += y;
    }
    if (lane == 31) wsum[wid] = x;
    __syncthreads();
    if (wid == 0) {
        int w = wsum[lane];
        #pragma unroll
        for (int off = 1; off < 32; off <<= 1) {
            int y = __shfl_up_sync(0xffffffffu, w, off);
            if (lane >= off) w += y;
        }
        wsum[lane] = w;
    }
    __syncthreads();
    const int incl = x + (wid > 0 ? wsum[wid - 1] : 0);
    if (tid == 1023) {
        g_bsum[bid] = incl;
        __threadfence();
        if (bid == 0) {
            g_bpre[0] = incl;
            __threadfence();
            atomicExch(&g_bflag[0], 2);
        } else {
            atomicExch(&g_bflag[bid], 1);
        }
    }
    if (tid == 0) {
        int off = 0;
        if (bid > 0) {
            int p = bid - 1;
            while (p >= 0) {
                int f;
                do { f = atomicAdd(&g_bflag[p], 0); } while (f == 0);
                if (f == 2) { off += atomicAdd(&g_bpre[p], 0); break; }
                off += atomicAdd(&g_bsum[p], 0);
                p--;
            }
        }
        s_off = off;
    }
    __syncthreads();
    const int off = s_off;
    if (i < NN) {
        int ex = off + incl - v;
        g_rowptr[i] = ex;
        g_cursor[i] = ex;
        if (i == NN - 1) g_rowptr[NN] = off + incl;
    }
    if (tid == 1023 && bid > 0) {
        g_bpre[bid] = off + incl;
        __threadfence();
        atomicExch(&g_bflag[bid], 2);
    }
}
__global__ void k_scatter(const int* __restrict__ ei) {
    int e = blockIdx.x * blockDim.x + threadIdx.x;
    if (e >= EE) return;
    int dst = ei[EE + e];
    int pos = atomicAdd(&g_cursor[dst], 1);
    g_col[pos] = ei[e];
}

// ---------- weight pack (full 13*DIN, unscaled) ----------
__global__ void k_packW(const float* __restrict__ W, uint4* __restrict__ dst,
                        int K13, int DOUT) {
    int KBW = K13 / 16;
    int total = (DOUT / 8) * KBW * 32;
    int t = blockIdx.x * blockDim.x + threadIdx.x;
    if (t >= total) return;
    int lane = t & 31;
    int kb = (t >> 5) % KBW;
    int nblk = (t >> 5) / KBW;
    int gr = lane >> 2, tig = lane & 3;
    int n = nblk * 8 + gr;
    int k0 = kb * 16 + tig * 2;
    float w00 = W[k0 * DOUT + n];
    float w01 = W[(k0 + 1) * DOUT + n];
    float w80 = W[(k0 + 8) * DOUT + n];
    float w81 = W[(k0 + 9) * DOUT + n];
    uint4 o;
    o.x = pk2(w00, w01);
    o.y = pk2(w80, w81);
    o.z = pk2(w00 - bfrt(w00), w01 - bfrt(w01));
    o.w = pk2(w80 - bfrt(w80), w81 - bfrt(w81));
    dst[t] = o;
}

// ---------- per-layer fold: x-region W *= s ; bias2 = b + t.W ----------
__global__ void k_foldW(const float* __restrict__ W, uint4* __restrict__ pW,
                        const float* __restrict__ borig,
                        int K13, int DOUT, int DIN) {
    int t = blockIdx.x * blockDim.x + threadIdx.x;
    int KBX = DIN / 16, KBW = K13 / 16;
    int total = (DOUT / 8) * KBX * 32;
    if (t < total) {
        int lane = t & 31;
        int kb = (t >> 5) % KBX;
        int nblk = (t >> 5) / KBX;
        int gr = lane >> 2, tig = lane & 3;
        int n = nblk * 8 + gr;
        int k0 = kb * 16 + tig * 2;
        float w00 = g_s[k0] * W[k0 * DOUT + n];
        float w01 = g_s[k0 + 1] * W[(k0 + 1) * DOUT + n];
        float w80 = g_s[k0 + 8] * W[(k0 + 8) * DOUT + n];
        float w81 = g_s[k0 + 9] * W[(k0 + 9) * DOUT + n];
        uint4 o;
        o.x = pk2(w00, w01);
        o.y = pk2(w80, w81);
        o.z = pk2(w00 - bfrt(w00), w01 - bfrt(w01));
        o.w = pk2(w80 - bfrt(w80), w81 - bfrt(w81));
        pW[(nblk * KBW + kb) * 32 + lane] = o;
    }
    if (t < DOUT) {
        float acc = borig[t];
        for (int k = 0; k < DIN; k++) acc = fmaf(g_t[k], W[k * DOUT + t], acc);
        g_bias2[t] = acc;
    }
}

// ---------- layer-1 X pack (raw) ----------
__global__ void k_packA(const float* __restrict__ src, uint4* __restrict__ dst,
                        int D) {
    __shared__ float sm[16][64];
    int tid = threadIdx.x;
    int gy = blockIdx.y * 64;
    #pragma unroll
    for (int tt = tid; tt < 256; tt += 128) {
        int row = tt >> 4, c4 = (tt & 15) * 4;
        int m = blockIdx.x * 16 + row;
        if (m >= NN) m = NN - 1;
        *(float4*)&sm[row][c4] = *(const float4*)(src + (size_t)m * D + gy + c4);
    }
    __syncthreads();
    int kb = tid >> 5, lane = tid & 31;
    int gr = lane >> 2, tig = lane & 3;
    int c0 = kb * 16 + tig * 2;
    float v[8];
    #pragma unroll
    for (int h = 0; h < 2; h++) {
        int c = c0 + h * 8;
        v[h * 4 + 0] = sm[gr][c];
        v[h * 4 + 1] = sm[gr][c + 1];
        v[h * 4 + 2] = sm[gr + 8][c];
        v[h * 4 + 3] = sm[gr + 8][c + 1];
    }
    uint4 hi, lo;
    hi.x = pk2(v[0], v[1]);
    hi.y = pk2(v[2], v[3]);
    hi.z = pk2(v[4], v[5]);
    hi.w = pk2(v[6], v[7]);
    lo.x = pk2(v[0] - bfrt(v[0]), v[1] - bfrt(v[1]));
    lo.y = pk2(v[2] - bfrt(v[2]), v[3] - bfrt(v[3]));
    lo.z = pk2(v[4] - bfrt(v[4]), v[5] - bfrt(v[5]));
    lo.w = pk2(v[6] - bfrt(v[6]), v[7] - bfrt(v[7]));
    int KB = D / 16;
    int idx = ((blockIdx.x * KB + (blockIdx.y * 4 + kb)) * 32 + lane) * 2;
    dst[idx] = hi;
    dst[idx + 1] = lo;
}

// ---------- fused aggregation + fragment pack (8-deep MLP) ----------
template <int DIN>
__global__ void __launch_bounds__(256) k_aggp(const float* __restrict__ in,
                                              uint4* __restrict__ pA) {
    constexpr int KBA = DIN / 4;
    __shared__ float sm[16][4][33];
    const int tid = threadIdx.x, lane = tid & 31, w = tid >> 5;
    const int nb = blockIdx.x * 16;
    const int c = blockIdx.y * 32 + lane;
    const float s = g_s[c], t = g_t[c];
    #pragma unroll
    for (int u = 0; u < 2; u++) {
        int nloc = w * 2 + u;
        int n = nb + nloc; if (n >= NN) n = NN - 1;
        int beg = g_rowptr[n], end = g_rowptr[n + 1];
        float sum = 0.f, ss = 0.f, mn = INFINITY, mx = -INFINITY;
        int j = beg;
        for (; j + 7 < end; j += 8) {
            int i0 = g_col[j], i1 = g_col[j + 1], i2 = g_col[j + 2], i3 = g_col[j + 3];
            int i4 = g_col[j + 4], i5 = g_col[j + 5], i6 = g_col[j + 6], i7 = g_col[j + 7];
            float v0 = in[i0 * DIN + c], v1 = in[i1 * DIN + c];
            float v2 = in[i2 * DIN + c], v3 = in[i3 * DIN + c];
            float v4 = in[i4 * DIN + c], v5 = in[i5 * DIN + c];
            float v6 = in[i6 * DIN + c], v7 = in[i7 * DIN + c];
            v0 = fmaf(s, v0, t); v1 = fmaf(s, v1, t);
            v2 = fmaf(s, v2, t); v3 = fmaf(s, v3, t);
            v4 = fmaf(s, v4, t); v5 = fmaf(s, v5, t);
            v6 = fmaf(s, v6, t); v7 = fmaf(s, v7, t);
            sum += (v0 + v1 + v2 + v3) + (v4 + v5 + v6 + v7);
            ss = fmaf(v0, v0, ss); ss = fmaf(v1, v1, ss);
            ss = fmaf(v2, v2, ss); ss = fmaf(v3, v3, ss);
            ss = fmaf(v4, v4, ss); ss = fmaf(v5, v5, ss);
            ss = fmaf(v6, v6, ss); ss = fmaf(v7, v7, ss);
            mn = fminf(mn, fminf(fminf(fminf(v0, v1), fminf(v2, v3)),
                                 fminf(fminf(v4, v5), fminf(v6, v7))));
            mx = fmaxf(mx, fmaxf(fmaxf(fmaxf(v0, v1), fmaxf(v2, v3)),
                                 fmaxf(fmaxf(v4, v5), fmaxf(v6, v7))));
        }
        for (; j + 3 < end; j += 4) {
            int i0 = g_col[j], i1 = g_col[j + 1], i2 = g_col[j + 2], i3 = g_col[j + 3];
            float v0 = in[i0 * DIN + c], v1 = in[i1 * DIN + c];
            float v2 = in[i2 * DIN + c], v3 = in[i3 * DIN + c];
            v0 = fmaf(s, v0, t); v1 = fmaf(s, v1, t);
            v2 = fmaf(s, v2, t); v3 = fmaf(s, v3, t);
            sum += v0 + v1 + v2 + v3;
            ss = fmaf(v0, v0, ss); ss = fmaf(v1, v1, ss);
            ss = fmaf(v2, v2, ss); ss = fmaf(v3, v3, ss);
            mn = fminf(mn, fminf(fminf(v0, v1), fminf(v2, v3)));
            mx = fmaxf(mx, fmaxf(fmaxf(v0, v1), fmaxf(v2, v3)));
        }
        for (; j < end; j++) {
            float v = fmaf(s, in[g_col[j] * DIN + c], t);
            sum += v; ss = fmaf(v, v, ss);
            mn = fminf(mn, v); mx = fmaxf(mx, v);
        }
        float deg = (float)(end - beg);
        float cnt = fmaxf(deg, 1.f);
        float mean = sum / cnt;
        float var = fmaxf(ss / cnt - mean * mean, 0.f);
        float sd = sqrtf(var + EPSW);
        bool has = end > beg;
        sm[nloc][0][lane] = mean;
        sm[nloc][1][lane] = has ? mn : 0.f;
        sm[nloc][2][lane] = has ? mx : 0.f;
        sm[nloc][3][lane] = sd;
    }
    __syncthreads();
    const int a = w >> 1, h = w & 1;
    const int gr = lane >> 2, tig = lane & 3;
    const int t2 = h * 16 + tig * 2;
    float v0 = sm[gr][a][t2],         v1 = sm[gr][a][t2 + 1];
    float v2 = sm[gr + 8][a][t2],     v3 = sm[gr + 8][a][t2 + 1];
    float v4 = sm[gr][a][t2 + 8],     v5 = sm[gr][a][t2 + 9];
    float v6 = sm[gr + 8][a][t2 + 8], v7 = sm[gr + 8][a][t2 + 9];
    uint4 hi, lo;
    hi.x = pk2(v0, v1); hi.y = pk2(v2, v3);
    hi.z = pk2(v4, v5); hi.w = pk2(v6, v7);
    lo.x = pk2(v0 - bfrt(v0), v1 - bfrt(v1));
    lo.y = pk2(v2 - bfrt(v2), v3 - bfrt(v3));
    lo.z = pk2(v4 - bfrt(v4), v5 - bfrt(v5));
    lo.w = pk2(v6 - bfrt(v6), v7 - bfrt(v7));
    const int kb = a * (DIN / 16) + blockIdx.y * 2 + h;
    int idx = ((blockIdx.x * KBA + kb) * 32 + lane) * 2;
    pA[idx] = hi;
    pA[idx + 1] = lo;
}

// ---------- bf16x2 3-pass fused PNA GEMM + epilogue fragment emit ----------
template <int DIN, int DOUT, bool WFRAG>
__global__ void __launch_bounds__(128) k_gemm_bf(const uint4* __restrict__ pX,
                                                 const uint4* __restrict__ pA,
                                                 const uint4* __restrict__ pW,
                                                 float* __restrict__ out,
                                                 uint4* __restrict__ pXout) {
    constexpr int KBX = DIN / 16;
    constexpr int KBA = DIN / 4;
    constexpr int KBW = 13 * DIN / 16;
    constexpr int KBN = DOUT / 16;
    __shared__ float scs[32], scss[32];
    const int tid = threadIdx.x, lane = tid & 31, wid = tid >> 5;
    const int warpM = wid & 1, warpN = wid >> 1;
    const int gr = lane >> 2, tig = lane & 3;
    const int mblk0 = blockIdx.x * 8 + warpM * 4;
    const int nblk0 = blockIdx.y * 4 + warpN * 2;

    if (tid < 32) { scs[tid] = 0.f; scss[tid] = 0.f; }

    float acc[3][4][2][4];
    #pragma unroll
    for (int s = 0; s < 3; s++)
        #pragma unroll
        for (int i = 0; i < 4; i++)
            #pragma unroll
            for (int j = 0; j < 2; j++)
                #pragma unroll
                for (int q = 0; q < 4; q++) acc[s][i][j][q] = 0.f;

    // ---- x region ----
    #pragma unroll 1
    for (int kb = 0; kb < KBX; kb++) {
        uint4 ah[4], al[4];
        #pragma unroll
        for (int i = 0; i < 4; i++) {
            int ai = (((mblk0 + i) * KBX + kb) * 32 + lane) * 2;
            ah[i] = pX[ai]; al[i] = pX[ai + 1];
        }
        #pragma unroll
        for (int j = 0; j < 2; j++) {
            uint4 b = pW[((nblk0 + j) * KBW + kb) * 32 + lane];
            #pragma unroll
            for (int i = 0; i < 4; i++) {
                mma16(acc[0][i][j], (const uint32_t*)&ah[i], b.x, b.y);
                mma16(acc[0][i][j], (const uint32_t*)&ah[i], b.z, b.w);
                mma16(acc[0][i][j], (const uint32_t*)&al[i], b.x, b.y);
            }
        }
    }
    // ---- aggs region ----
    #pragma unroll 1
    for (int kb = 0; kb < KBA; kb++) {
        uint4 ah[4], al[4];
        #pragma unroll
        for (int i = 0; i < 4; i++) {
            int ai = (((mblk0 + i) * KBA + kb) * 32 + lane) * 2;
            ah[i] = pA[ai]; al[i] = pA[ai + 1];
        }
        #pragma unroll
        for (int s = 0; s < 3; s++) {
            const int kbg = KBX + s * KBA + kb;
            #pragma unroll
            for (int j = 0; j < 2; j++) {
                uint4 b = pW[((nblk0 + j) * KBW + kbg) * 32 + lane];
                #pragma unroll
                for (int i = 0; i < 4; i++) {
                    mma16(acc[s][i][j], (const uint32_t*)&ah[i], b.x, b.y);
                    mma16(acc[s][i][j], (const uint32_t*)&ah[i], b.z, b.w);
                    mma16(acc[s][i][j], (const uint32_t*)&al[i], b.x, b.y);
                }
            }
        }
    }
    __syncthreads();

    // ---- epilogue ----
    const int m0w = blockIdx.x * 128 + warpM * 64;
    const int n0w = blockIdx.y * 32 + warpN * 16;
    const int kbn = blockIdx.y * 2 + warpN;
    float cs[2][2], css[2][2];
    #pragma unroll
    for (int j = 0; j < 2; j++) { cs[j][0] = 0.f; cs[j][1] = 0.f; css[j][0] = 0.f; css[j][1] = 0.f; }

    #pragma unroll
    for (int i = 0; i < 4; i++) {
        int ra = m0w + i * 16 + gr, rb = ra + 8;
        int rac = ra < NN ? ra : NN - 1, rbc = rb < NN ? rb : NN - 1;
        float ampa = g_amp[rac], ampb = g_amp[rbc];
        float atta = g_att[rac], attb = g_att[rbc];
        float vj[2][4];
        #pragma unroll
        for (int j = 0; j < 2; j++) {
            int col = n0w + j * 8 + tig * 2;
            float bs0 = g_bias2[col], bs1 = g_bias2[col + 1];
            vj[j][0] = fmaxf(acc[0][i][j][0] + ampa * acc[1][i][j][0] +
                             atta * acc[2][i][j][0] + bs0, 0.f);
            vj[j][1] = fmaxf(acc[0][i][j][1] + ampa * acc[1][i][j][1] +
                             atta * acc[2][i][j][1] + bs1, 0.f);
            vj[j][2] = fmaxf(acc[0][i][j][2] + ampb * acc[1][i][j][2] +
                             attb * acc[2][i][j][2] + bs0, 0.f);
            vj[j][3] = fmaxf(acc[0][i][j][3] + ampb * acc[1][i][j][3] +
                             attb * acc[2][i][j][3] + bs1, 0.f);
            if (ra < NN) {
                *(float2*)(out + ra * DOUT + col) = make_float2(vj[j][0], vj[j][1]);
                cs[j][0] += vj[j][0]; css[j][0] = fmaf(vj[j][0], vj[j][0], css[j][0]);
                cs[j][1] += vj[j][1]; css[j][1] = fmaf(vj[j][1], vj[j][1], css[j][1]);
            }
            if (rb < NN) {
                *(float2*)(out + rb * DOUT + col) = make_float2(vj[j][2], vj[j][3]);
                cs[j][0] += vj[j][2]; css[j][0] = fmaf(vj[j][2], vj[j][2], css[j][0]);
                cs[j][1] += vj[j][3]; css[j][1] = fmaf(vj[j][3], vj[j][3], css[j][1]);
            }
        }
        if (WFRAG) {
            uint4 hi, lo;
            hi.x = pk2(vj[0][0], vj[0][1]);
            hi.y = pk2(vj[0][2], vj[0][3]);
            hi.z = pk2(vj[1][0], vj[1][1]);
            hi.w = pk2(vj[1][2], vj[1][3]);
            lo.x = pk2(vj[0][0] - bfrt(vj[0][0]), vj[0][1] - bfrt(vj[0][1]));
            lo.y = pk2(vj[0][2] - bfrt(vj[0][2]), vj[0][3] - bfrt(vj[0][3]));
            lo.z = pk2(vj[1][0] - bfrt(vj[1][0]), vj[1][1] - bfrt(vj[1][1]));
            lo.w = pk2(vj[1][2] - bfrt(vj[1][2]), vj[1][3] - bfrt(vj[1][3]));
            int fi = (((mblk0 + i) * KBN + kbn) * 32 + lane) * 2;
            pXout[fi] = hi;
            pXout[fi + 1] = lo;
        }
    }
    #pragma unroll
    for (int j = 0; j < 2; j++) {
        float a0 = cs[j][0], b0 = css[j][0], a1 = cs[j][1], b1 = css[j][1];
        #pragma unroll
        for (int off = 16; off >= 4; off >>= 1) {
            a0 += __shfl_xor_sync(0xffffffffu, a0, off);
            b0 += __shfl_xor_sync(0xffffffffu, b0, off);
            a1 += __shfl_xor_sync(0xffffffffu, a1, off);
            b1 += __shfl_xor_sync(0xffffffffu, b1, off);
        }
        if (gr == 0) {
            int lc = warpN * 16 + j * 8 + tig * 2;
            atomicAdd(&scs[lc], a0);
            atomicAdd(&scss[lc], b0);
            atomicAdd(&scs[lc + 1], a1);
            atomicAdd(&scss[lc + 1], b1);
        }
    }
    __syncthreads();
    if (tid < 32) {
        atomicAdd(&g_colsum[blockIdx.y * 32 + tid], scs[tid]);
        atomicAdd(&g_colsumsq[blockIdx.y * 32 + tid], scss[tid]);
    }
}

// stats + re-zero accumulators
__global__ void k_stats(const float* __restrict__ gamma,
                        const float* __restrict__ beta, int dout) {
    int c = threadIdx.x;
    if (c < dout) {
        float mean = g_colsum[c] / (float)NN;
        float var = fmaxf(g_colsumsq[c] / (float)NN - mean * mean, 0.f);
        float sc = gamma[c] * rsqrtf(var + EPSW);
        g_s[c] = sc;
        g_t[c] = beta[c] - mean * sc;
    }
    __syncthreads();
    if (c < 256) { g_colsum[c] = 0.f; g_colsumsq[c] = 0.f; }
}

// ---------- classifier ----------
__global__ void k_foldcls(const float* __restrict__ Wc, const float* __restrict__ bc) {
    int tid = threadIdx.x;
    if (tid < 640) {
        int c = tid / 10;
        g_wc2[tid] = g_s[c] * Wc[tid];
    }
    if (tid < 10) {
        float acc = bc[tid];
        for (int c = 0; c < 64; c++) acc = fmaf(g_t[c], Wc[c * 10 + tid], acc);
        g_bc2[tid] = acc;
    }
}
__global__ void k_cls(const float* __restrict__ r, float* __restrict__ out) {
    __shared__ float w[640];
    __shared__ float b[10];
    int tid = threadIdx.x;
    for (int i = tid; i < 640; i += blockDim.x) w[i] = g_wc2[i];
    if (tid < 10) b[tid] = g_bc2[tid];
    __syncthreads();
    int warp = (blockIdx.x * blockDim.x + tid) >> 5;
    int lane = tid & 31;
    if (warp >= NN) return;
    float v0 = r[(size_t)warp * 64 + lane];
    float v1 = r[(size_t)warp * 64 + 32 + lane];
    float acc[10];
    #pragma unroll
    for (int j = 0; j < 10; j++)
        acc[j] = v0 * w[lane * 10 + j] + v1 * w[(32 + lane) * 10 + j];
    #pragma unroll
    for (int off = 16; off; off >>= 1)
        #pragma unroll
        for (int j = 0; j < 10; j++)
            acc[j] += __shfl_xor_sync(0xffffffffu, acc[j], off);
    if (lane < 10) out[(size_t)warp * 10 + lane] = acc[lane] + b[lane];
}

// ---------- launch ----------
extern "C" void kernel_launch(void* const* d_in, const int* in_sizes, int n_in,
                              void* d_out, int out_size) {
    const float* x  = (const float*)d_in[0];
    const int*   ei = (const int*)d_in[1];
    const float* W1 = (const float*)d_in[2];
    const float* b1 = (const float*)d_in[3];
    const float* ga1 = (const float*)d_in[4];
    const float* be1 = (const float*)d_in[5];
    const float* W2 = (const float*)d_in[6];
    const float* b2 = (const float*)d_in[7];
    const float* ga2 = (const float*)d_in[8];
    const float* be2 = (const float*)d_in[9];
    const float* W3 = (const float*)d_in[10];
    const float* b3 = (const float*)d_in[11];
    const float* ga3 = (const float*)d_in[12];
    const float* be3 = (const float*)d_in[13];
    const float* W4 = (const float*)d_in[14];
    const float* b4 = (const float*)d_in[15];
    const float* ga4 = (const float*)d_in[16];
    const float* be4 = (const float*)d_in[17];
    const float* Wc = (const float*)d_in[18];
    const float* bc = (const float*)d_in[19];
    float* out = (float*)d_out;

    float *p_h0, *p_h1;
    uint4 *pX0, *pX1, *pA, *pw1, *pw2, *pw3, *pw4;
    cudaGetSymbolAddress((void**)&p_h0, g_h0);
    cudaGetSymbolAddress((void**)&p_h1, g_h1);
    cudaGetSymbolAddress((void**)&pX0, g_pX0);
    cudaGetSymbolAddress((void**)&pX1, g_pX1);
    cudaGetSymbolAddress((void**)&pA, g_packAgg);
    cudaGetSymbolAddress((void**)&pw1, g_wp1);
    cudaGetSymbolAddress((void**)&pw2, g_wp2);
    cudaGetSymbolAddress((void**)&pw3, g_wp3);
    cudaGetSymbolAddress((void**)&pw4, g_wp4);

    // preprocessing
    k_init<<<(NN + 255) / 256, 256>>>();
    k_degcnt<<<EE / 256, 256>>>(ei);
    k_logdeg<<<(NN + 255) / 256, 256>>>();
    k_scan2<<<SCAN_BLOCKS, 1024>>>();
    k_scatter<<<EE / 256, 256>>>(ei);

    // ---- layer 1: 64 -> 128 ----
    k_aggp<64><<<dim3(NBLK16, 2), 256>>>(x, pA);
    k_packW<<<(16 * 52 * 32 + 255) / 256, 256>>>(W1, pw1, 832, 128);
    k_packW<<<(32 * 104 * 32 + 255) / 256, 256>>>(W2, pw2, 1664, 256);
    k_packW<<<(16 * 208 * 32 + 255) / 256, 256>>>(W3, pw3, 3328, 128);
    k_packW<<<(8 * 104 * 32 + 255) / 256, 256>>>(W4, pw4, 1664, 64);
    k_packA<<<dim3(NBLK16, 1), 128>>>(x, pX0, 64);
    k_foldW<<<8, 256>>>(W1, pw1, b1, 832, 128, 64);        // s=1,t=0 here
    k_gemm_bf<64, 128, true><<<dim3(NPAD / 128, 4), 128>>>(pX0, pA, pw1, p_h0, pX1);
    k_stats<<<1, 256>>>(ga1, be1, 128);

    // ---- layer 2: 128 -> 256 ----
    k_aggp<128><<<dim3(NBLK16, 4), 256>>>(p_h0, pA);
    k_foldW<<<32, 256>>>(W2, pw2, b2, 1664, 256, 128);
    k_gemm_bf<128, 256, true><<<dim3(NPAD / 128, 8), 128>>>(pX1, pA, pw2, p_h1, pX0);
    k_stats<<<1, 256>>>(ga2, be2, 256);

    // ---- layer 3: 256 -> 128 ----
    k_aggp<256><<<dim3(NBLK16, 8), 256>>>(p_h1, pA);
    k_foldW<<<32, 256>>>(W3, pw3, b3, 3328, 128, 256);
    k_gemm_bf<256, 128, true><<<dim3(NPAD / 128, 4), 128>>>(pX0, pA, pw3, p_h0, pX1);
    k_stats<<<1, 256>>>(ga3, be3, 128);

    // ---- layer 4: 128 -> 64 ----
    k_aggp<128><<<dim3(NBLK16, 4), 256>>>(p_h0, pA);
    k_foldW<<<8, 256>>>(W4, pw4, b4, 1664, 64, 128);
    k_gemm_bf<128, 64, false><<<dim3(NPAD / 128, 2), 128>>>(pX1, pA, pw4, p_h1, pX0);
    k_stats<<<1, 256>>>(ga4, be4, 64);

    // ---- classifier ----
    k_foldcls<<<1, 640>>>(Wc, bc);
    k_cls<<<((size_t)NN * 32 + 255) / 256, 256>>>(p_h1, out);
}